// round 7
// baseline (speedup 1.0000x reference)
#include <cuda_runtime.h>
#include <cuda_fp16.h>
#include <math.h>

#define NN 50000
#define EE 600000
#define CC 128
#define KK 128
#define SCAN_BLOCKS ((NN + 255) / 256)   // 196
#define LDH 136                           // padded smem row, halves

// Scratch (static device globals; no runtime allocation allowed)
__device__ float  g_out[(size_t)NN * CC];      // softplus(h@W0+b0) fp32
__device__ __half g_out16[(size_t)NN * CC];    // fp16 copy (A of TC GEMM)
__device__ float  g_Pi[(size_t)NN * 256];      // fp32 [pi_f | pi_s] per node
__device__ __half g_Pj16[(size_t)NN * 256];    // fp16 [pj_f | pj_s] per node
__device__ float  g_aggr[(size_t)NN * CC];     // segment-sum result
__device__ float  g_stats[2 * CC];             // per-channel sum, sumsq
__device__ __half g_Wcat16T[512 * 128];        // packed weights, TRANSPOSED [n][k], fp16
// CSR scratch
__device__ int    g_deg[NN];
__device__ int    g_roff[NN];
__device__ int    g_cursor[NN];
__device__ int    g_bsum[SCAN_BLOCKS];
__device__ int    g_boff[SCAN_BLOCKS];
__device__ int2   g_epack[EE];                 // (src, e-bits) sorted by dst

__device__ __forceinline__ float sp_f(float x) {
    return x > 15.0f ? x : __logf(1.0f + __expf(x));
}
// sigmoid via MUFU tanh: 1 MUFU + 1 FMA (vs exp+rcp = 2 MUFU)
__device__ __forceinline__ float sigm_f(float x) {
    float t;
    asm("tanh.approx.f32 %0, %1;" : "=f"(t) : "f"(x * 0.5f));
    return fmaf(0.5f, t, 0.5f);
}

// ---------------- weight packing (fp16, transposed [n][k]) ----------------
__global__ void prep_wcat(const float* __restrict__ Wf, const float* __restrict__ Ws) {
    int idx = blockIdx.x * blockDim.x + threadIdx.x;   // n*128 + k
    if (idx >= 512 * 128) return;
    int n = idx >> 7;
    int k = idx & 127;
    float v;
    if (n < 128)      v = Wf[k * 128 + n];
    else if (n < 256) v = Ws[k * 128 + (n - 128)];
    else if (n < 384) v = Wf[(128 + k) * 128 + (n - 256)];
    else              v = Ws[(128 + k) * 128 + (n - 384)];
    g_Wcat16T[idx] = __float2half(v);
}

// ---------------- GEMM1 (fp32 SIMT): out = softplus(h@W0 + b0), + fp16 copy ----
__global__ void __launch_bounds__(256, 2)
gemm1(const float* __restrict__ A, const float* __restrict__ B,
      const float* __restrict__ bias, int M) {
    __shared__ float As[16][132];
    __shared__ float Bs[16][128];
    int tid = threadIdx.x;
    int tx = tid & 15, ty = tid >> 4;
    int row0 = blockIdx.x * 128;
    float acc[8][8] = {};

    for (int kc = 0; kc < KK; kc += 16) {
#pragma unroll
        for (int l = 0; l < 2; l++) {
            int f = tid + l * 256;
            int m = f >> 2;
            int kq = (f & 3) << 2;
            int gr = row0 + m;
            float4 av = make_float4(0.f, 0.f, 0.f, 0.f);
            if (gr < M) av = *(const float4*)(A + (size_t)gr * KK + kc + kq);
            As[kq + 0][m] = av.x;
            As[kq + 1][m] = av.y;
            As[kq + 2][m] = av.z;
            As[kq + 3][m] = av.w;
        }
#pragma unroll
        for (int l = 0; l < 2; l++) {
            int f = tid + l * 256;
            int k = f >> 5;
            int c4 = (f & 31) << 2;
            *(float4*)&Bs[k][c4] = *(const float4*)(B + (size_t)(kc + k) * CC + c4);
        }
        __syncthreads();
#pragma unroll
        for (int k = 0; k < 16; k++) {
            float4 a0 = *(float4*)&As[k][ty * 4];
            float4 a1 = *(float4*)&As[k][64 + ty * 4];
            float4 b0 = *(float4*)&Bs[k][tx * 4];
            float4 b1 = *(float4*)&Bs[k][64 + tx * 4];
            float ar[8] = {a0.x, a0.y, a0.z, a0.w, a1.x, a1.y, a1.z, a1.w};
            float br[8] = {b0.x, b0.y, b0.z, b0.w, b1.x, b1.y, b1.z, b1.w};
#pragma unroll
            for (int i = 0; i < 8; i++)
#pragma unroll
                for (int j = 0; j < 8; j++)
                    acc[i][j] += ar[i] * br[j];
        }
        __syncthreads();
    }

#pragma unroll
    for (int i = 0; i < 8; i++) {
        int gr = row0 + (i < 4 ? ty * 4 + i : 64 + ty * 4 + (i - 4));
        if (gr >= M) continue;
#pragma unroll
        for (int half = 0; half < 2; half++) {
            int gc = half * 64 + tx * 4;
            float4 v;
            v.x = sp_f(acc[i][half * 4 + 0] + bias[gc + 0]);
            v.y = sp_f(acc[i][half * 4 + 1] + bias[gc + 1]);
            v.z = sp_f(acc[i][half * 4 + 2] + bias[gc + 2]);
            v.w = sp_f(acc[i][half * 4 + 3] + bias[gc + 3]);
            *(float4*)(g_out + (size_t)gr * CC + gc) = v;
            __half2 h0 = __floats2half2_rn(v.x, v.y);
            __half2 h1 = __floats2half2_rn(v.z, v.w);
            uint2 u;
            u.x = *(unsigned*)&h0;
            u.y = *(unsigned*)&h1;
            *(uint2*)(g_out16 + (size_t)gr * CC + gc) = u;
        }
    }
}

// ---------------- GEMM2 (fp16 tensor core): P = out @ Wcat ----------------
__global__ void __launch_bounds__(256, 2)
gemm2_tc() {
    extern __shared__ __half smemh[];
    __half* As = smemh;                 // [128][LDH]
    __half* Bs = smemh + 128 * LDH;     // [128][LDH], row n, col k
    int tid = threadIdx.x;
    int row0 = blockIdx.x * 128;
    int nblk = blockIdx.y;

#pragma unroll
    for (int l = 0; l < 8; l++) {
        int idx = tid + l * 256;
        int r = idx >> 4;
        int c8 = (idx & 15) << 3;
        int4 v = make_int4(0, 0, 0, 0);
        int gr = row0 + r;
        if (gr < NN) v = *(const int4*)(g_out16 + (size_t)gr * CC + c8);
        *(int4*)(As + r * LDH + c8) = v;
        int4 w = *(const int4*)(g_Wcat16T + ((size_t)(nblk * 128 + r)) * CC + c8);
        *(int4*)(Bs + r * LDH + c8) = w;
    }
    __syncthreads();

    int lane = tid & 31;
    int w = tid >> 5;
    int g = lane >> 2, tig = lane & 3;
    int wm = (w & 1) * 64, wn = (w >> 1) * 32;

    float acc[4][4][4];
#pragma unroll
    for (int mt = 0; mt < 4; mt++)
#pragma unroll
        for (int nt = 0; nt < 4; nt++)
#pragma unroll
            for (int q = 0; q < 4; q++) acc[mt][nt][q] = 0.f;

    const unsigned* As2 = (const unsigned*)As;
    const unsigned* Bs2 = (const unsigned*)Bs;

#pragma unroll
    for (int ks = 0; ks < 8; ks++) {
        int kk = ks * 8;
        unsigned a[4][4], b[4][2];
#pragma unroll
        for (int mt = 0; mt < 4; mt++) {
            int r = wm + mt * 16 + g;
            a[mt][0] = As2[r * 68 + kk + tig];
            a[mt][1] = As2[(r + 8) * 68 + kk + tig];
            a[mt][2] = As2[r * 68 + kk + 4 + tig];
            a[mt][3] = As2[(r + 8) * 68 + kk + 4 + tig];
        }
#pragma unroll
        for (int nt = 0; nt < 4; nt++) {
            int r = wn + nt * 8 + g;
            b[nt][0] = Bs2[r * 68 + kk + tig];
            b[nt][1] = Bs2[r * 68 + kk + 4 + tig];
        }
#pragma unroll
        for (int mt = 0; mt < 4; mt++)
#pragma unroll
            for (int nt = 0; nt < 4; nt++) {
                asm volatile(
                    "mma.sync.aligned.m16n8k16.row.col.f32.f16.f16.f32 "
                    "{%0,%1,%2,%3}, {%4,%5,%6,%7}, {%8,%9}, {%0,%1,%2,%3};"
                    : "+f"(acc[mt][nt][0]), "+f"(acc[mt][nt][1]),
                      "+f"(acc[mt][nt][2]), "+f"(acc[mt][nt][3])
                    : "r"(a[mt][0]), "r"(a[mt][1]), "r"(a[mt][2]), "r"(a[mt][3]),
                      "r"(b[nt][0]), "r"(b[nt][1]));
            }
    }

#pragma unroll
    for (int mt = 0; mt < 4; mt++) {
#pragma unroll
        for (int nt = 0; nt < 4; nt++) {
            int gr0 = row0 + wm + mt * 16 + g;
            int gr1 = gr0 + 8;
            int col = nblk * 128 + wn + nt * 8 + tig * 2;
            float d0 = acc[mt][nt][0], d1 = acc[mt][nt][1];
            float d2 = acc[mt][nt][2], d3 = acc[mt][nt][3];
            if (nblk < 2) {
                if (gr0 < NN) *(float2*)(g_Pi + (size_t)gr0 * 256 + col) = make_float2(d0, d1);
                if (gr1 < NN) *(float2*)(g_Pi + (size_t)gr1 * 256 + col) = make_float2(d2, d3);
            } else {
                int cj = col - 256;
                __half2 h01 = __floats2half2_rn(d0, d1);
                __half2 h23 = __floats2half2_rn(d2, d3);
                if (gr0 < NN) *(unsigned*)(g_Pj16 + (size_t)gr0 * 256 + cj) = *(unsigned*)&h01;
                if (gr1 < NN) *(unsigned*)(g_Pj16 + (size_t)gr1 * 256 + cj) = *(unsigned*)&h23;
            }
        }
    }
}

// ---------------- CSR build ----------------
__global__ void hist(const int* __restrict__ ei) {
    int e = blockIdx.x * blockDim.x + threadIdx.x;
    if (e < EE) atomicAdd(&g_deg[ei[EE + e]], 1);
}

__global__ void scan_local() {
    __shared__ int s[256];
    int tid = threadIdx.x;
    int i = blockIdx.x * 256 + tid;
    int v = (i < NN) ? g_deg[i] : 0;
    s[tid] = v;
    __syncthreads();
#pragma unroll
    for (int off = 1; off < 256; off <<= 1) {
        int t = (tid >= off) ? s[tid - off] : 0;
        __syncthreads();
        s[tid] += t;
        __syncthreads();
    }
    if (i < NN) g_roff[i] = s[tid] - v;
    if (tid == 255) g_bsum[blockIdx.x] = s[255];
}

__global__ void scan_bsums() {
    __shared__ int s[256];
    int tid = threadIdx.x;
    int v = (tid < SCAN_BLOCKS) ? g_bsum[tid] : 0;
    s[tid] = v;
    __syncthreads();
#pragma unroll
    for (int off = 1; off < 256; off <<= 1) {
        int t = (tid >= off) ? s[tid - off] : 0;
        __syncthreads();
        s[tid] += t;
        __syncthreads();
    }
    if (tid < SCAN_BLOCKS) g_boff[tid] = s[tid] - v;
}

__global__ void scan_add() {
    int i = blockIdx.x * 256 + threadIdx.x;
    if (i < NN) {
        int r = g_roff[i] + g_boff[blockIdx.x];
        g_roff[i] = r;
        g_cursor[i] = r;
    }
}

// ---------------- e = softplus(edge_attr @ Wsh + bsh) fused with CSR scatter
// 8 lanes per edge; each lane loads 4 contiguous float4 (64B, MLP=4); 3-shfl reduce.
__global__ void edge_gauss_scatter(const float* __restrict__ ea,
                                   const float* __restrict__ Wsh,
                                   const float* __restrict__ bsh,
                                   const int* __restrict__ ei) {
    int t = blockIdx.x * blockDim.x + threadIdx.x;
    int e = t >> 3;
    if (e >= EE) return;
    int l = t & 7;
    const float4* base = (const float4*)(ea + (size_t)e * 128) + l * 4;
    const float4* wb = (const float4*)Wsh + l * 4;
    float4 a0 = base[0], a1 = base[1], a2 = base[2], a3 = base[3];
    float4 w0 = wb[0], w1 = wb[1], w2 = wb[2], w3 = wb[3];
    float d = a0.x * w0.x + a0.y * w0.y + a0.z * w0.z + a0.w * w0.w
            + a1.x * w1.x + a1.y * w1.y + a1.z * w1.z + a1.w * w1.w
            + a2.x * w2.x + a2.y * w2.y + a2.z * w2.z + a2.w * w2.w
            + a3.x * w3.x + a3.y * w3.y + a3.z * w3.z + a3.w * w3.w;
#pragma unroll
    for (int o = 4; o; o >>= 1) d += __shfl_xor_sync(0xFFFFFFFFu, d, o);
    if (l == 0) {
        float ev = sp_f(d + bsh[0]);
        int src = __ldg(ei + e);
        int dst = __ldg(ei + EE + e);
        int pos = atomicAdd(&g_cursor[dst], 1);
        g_epack[pos] = make_int2(src, __float_as_int(ev));
    }
}

// ---------------- CSR edge messages + fused BN stats ----------------
__device__ __forceinline__ void pj_load(int src, int lane, float4& f, float4& q) {
    const __half* base = g_Pj16 + (size_t)src * 256;
    uint2 uf = *(const uint2*)(base + lane * 4);
    uint2 uq = *(const uint2*)(base + 128 + lane * 4);
    float2 f01 = __half22float2(*(__half2*)&uf.x);
    float2 f23 = __half22float2(*(__half2*)&uf.y);
    float2 q01 = __half22float2(*(__half2*)&uq.x);
    float2 q23 = __half22float2(*(__half2*)&uq.y);
    f = make_float4(f01.x, f01.y, f23.x, f23.y);
    q = make_float4(q01.x, q01.y, q23.x, q23.y);
}

__device__ __forceinline__ void msg_add(float4& acc, const float4& pif, const float4& pis,
                                        const float4& f, const float4& q, float ev,
                                        const float4& wfe, const float4& wse) {
    acc.x += sigm_f(pif.x + f.x + ev * wfe.x) * sp_f(pis.x + q.x + ev * wse.x);
    acc.y += sigm_f(pif.y + f.y + ev * wfe.y) * sp_f(pis.y + q.y + ev * wse.y);
    acc.z += sigm_f(pif.z + f.z + ev * wfe.z) * sp_f(pis.z + q.z + ev * wse.z);
    acc.w += sigm_f(pif.w + f.w + ev * wfe.w) * sp_f(pis.w + q.w + ev * wse.w);
}

__global__ void __launch_bounds__(256)
edge_msg_csr(const float* __restrict__ Wf, const float* __restrict__ Ws,
             const float* __restrict__ bf, const float* __restrict__ bs,
             int nwarps) {
    __shared__ float s_stats[2 * CC];
    int tid = threadIdx.x;
    int lane = tid & 31;
    int c = lane * 4;
    s_stats[tid] = 0.0f;
    __syncthreads();

    float4 wfe = *(const float4*)(Wf + 256 * 128 + c);
    float4 wse = *(const float4*)(Ws + 256 * 128 + c);
    float4 bfv = *(const float4*)(bf + c);
    float4 bsv = *(const float4*)(bs + c);

    float lsum[4] = {}, lsq[4] = {};

    int gw = blockIdx.x * 8 + (tid >> 5);
    for (int i = gw; i < NN; i += nwarps) {
        const float4* Pi = (const float4*)(g_Pi + (size_t)i * 256);
        float4 pif = Pi[lane];
        float4 pis = Pi[32 + lane];
        pif.x += bfv.x; pif.y += bfv.y; pif.z += bfv.z; pif.w += bfv.w;
        pis.x += bsv.x; pis.y += bsv.y; pis.z += bsv.z; pis.w += bsv.w;
        int k = g_roff[i];
        int end = g_cursor[i];
        float4 acc = make_float4(0.f, 0.f, 0.f, 0.f);

        for (; k + 4 <= end; k += 4) {
            int2 p0 = g_epack[k], p1 = g_epack[k + 1], p2 = g_epack[k + 2], p3 = g_epack[k + 3];
            float4 f0, q0, f1, q1, f2, q2, f3, q3;
            pj_load(p0.x, lane, f0, q0);
            pj_load(p1.x, lane, f1, q1);
            pj_load(p2.x, lane, f2, q2);
            pj_load(p3.x, lane, f3, q3);
            msg_add(acc, pif, pis, f0, q0, __int_as_float(p0.y), wfe, wse);
            msg_add(acc, pif, pis, f1, q1, __int_as_float(p1.y), wfe, wse);
            msg_add(acc, pif, pis, f2, q2, __int_as_float(p2.y), wfe, wse);
            msg_add(acc, pif, pis, f3, q3, __int_as_float(p3.y), wfe, wse);
        }
        for (; k < end; k++) {
            int2 p0 = g_epack[k];
            float4 f0, q0;
            pj_load(p0.x, lane, f0, q0);
            msg_add(acc, pif, pis, f0, q0, __int_as_float(p0.y), wfe, wse);
        }
        *(float4*)(g_aggr + (size_t)i * CC + c) = acc;
        lsum[0] += acc.x; lsum[1] += acc.y; lsum[2] += acc.z; lsum[3] += acc.w;
        lsq[0] += acc.x * acc.x; lsq[1] += acc.y * acc.y; lsq[2] += acc.z * acc.z; lsq[3] += acc.w * acc.w;
    }

#pragma unroll
    for (int j = 0; j < 4; j++) {
        atomicAdd(&s_stats[c + j], lsum[j]);
        atomicAdd(&s_stats[CC + c + j], lsq[j]);
    }
    __syncthreads();
    if (tid < 64) {
        float4 v = *(float4*)&s_stats[tid * 4];
        float* dstp = g_stats + tid * 4;
        asm volatile("red.global.add.v4.f32 [%0], {%1, %2, %3, %4};"
                     :: "l"(dstp), "f"(v.x), "f"(v.y), "f"(v.z), "f"(v.w)
                     : "memory");
    }
}

// ---------------- out_final = 2*out + batchnorm(aggr) ----------------
__global__ void finalize(const float* __restrict__ gamma, const float* __restrict__ beta,
                         float* __restrict__ out) {
    int i4 = blockIdx.x * blockDim.x + threadIdx.x;
    if (i4 >= NN * 32) return;
    int c = (i4 & 31) * 4;
    float4 a = *(const float4*)(g_aggr + (size_t)i4 * 4);
    float4 o = *(const float4*)(g_out + (size_t)i4 * 4);
    const float inv = 1.0f / NN;
    float4 r;
#pragma unroll
    for (int j = 0; j < 4; j++) {
        float sum = g_stats[c + j];
        float sq = g_stats[CC + c + j];
        float mean = sum * inv;
        float var = sq * inv - mean * mean;
        float scale = rsqrtf(var + 1e-5f) * gamma[c + j];
        float av = (&a.x)[j];
        float ov = (&o.x)[j];
        (&r.x)[j] = 2.0f * ov + (av - mean) * scale + beta[c + j];
    }
    *(float4*)(out + (size_t)i4 * 4) = r;
}

extern "C" void kernel_launch(void* const* d_in, const int* in_sizes, int n_in,
                              void* d_out, int out_size) {
    const float* h    = (const float*)d_in[0];
    const int*   ei   = (const int*)d_in[1];
    const float* ea   = (const float*)d_in[3];
    const float* W0   = (const float*)d_in[4];
    const float* b0   = (const float*)d_in[5];
    const float* Wsh  = (const float*)d_in[6];
    const float* bsh  = (const float*)d_in[7];
    const float* Wf   = (const float*)d_in[8];
    const float* bf   = (const float*)d_in[9];
    const float* Ws   = (const float*)d_in[10];
    const float* bs   = (const float*)d_in[11];
    const float* gamma = (const float*)d_in[12];
    const float* beta  = (const float*)d_in[13];
    float* out = (float*)d_out;

    float *p_stats;
    int *p_deg;
    cudaGetSymbolAddress((void**)&p_stats, g_stats);
    cudaGetSymbolAddress((void**)&p_deg, g_deg);

    static cudaStream_t s2 = nullptr;
    static cudaEvent_t evFork = nullptr, evJoin = nullptr;
    static bool attrSet = false;
    if (!s2) {
        cudaStreamCreateWithFlags(&s2, cudaStreamNonBlocking);
        cudaEventCreateWithFlags(&evFork, cudaEventDisableTiming);
        cudaEventCreateWithFlags(&evJoin, cudaEventDisableTiming);
    }
    if (!attrSet) {
        cudaFuncSetAttribute(gemm2_tc, cudaFuncAttributeMaxDynamicSharedMemorySize,
                             2 * 128 * LDH * (int)sizeof(__half));
        attrSet = true;
    }

    // ---- fork: edge/CSR pipeline on s2, node/GEMM pipeline on default ----
    cudaEventRecord(evFork, 0);
    cudaStreamWaitEvent(s2, evFork, 0);

    cudaMemsetAsync(p_deg, 0, NN * sizeof(int), s2);
    hist<<<(EE + 255) / 256, 256, 0, s2>>>(ei);
    scan_local<<<SCAN_BLOCKS, 256, 0, s2>>>();
    scan_bsums<<<1, 256, 0, s2>>>();
    scan_add<<<SCAN_BLOCKS, 256, 0, s2>>>();
    edge_gauss_scatter<<<(EE * 8 + 255) / 256, 256, 0, s2>>>(ea, Wsh, bsh, ei);
    cudaEventRecord(evJoin, s2);

    cudaMemsetAsync(p_stats, 0, 2 * CC * sizeof(float));
    prep_wcat<<<(512 * 128 + 255) / 256, 256>>>(Wf, Ws);
    gemm1<<<(NN + 127) / 128, 256>>>(h, W0, b0, NN);
    gemm2_tc<<<dim3((NN + 127) / 128, 4), 256, 2 * 128 * LDH * sizeof(__half)>>>();

    cudaStreamWaitEvent(0, evJoin, 0);

    const int blocks = 1024;
    edge_msg_csr<<<blocks, 256>>>(Wf, Ws, bf, bs, blocks * 8);
    finalize<<<(NN * 32 + 255) / 256, 256>>>(gamma, beta, out);
}

// round 9
// speedup vs baseline: 1.0029x; 1.0029x over previous
#include <cuda_runtime.h>
#include <cuda_fp16.h>
#include <math.h>

#define NN 50000
#define EE 600000
#define CC 128
#define KK 128
#define LDH 136                           // padded smem row, halves

// Scratch (static device globals; no runtime allocation allowed)
__device__ float  g_out[(size_t)NN * CC];      // softplus(h@W0+b0) fp32
__device__ __half g_out16[(size_t)NN * CC];    // fp16 copy (A of TC GEMM)
__device__ float  g_Pi[(size_t)NN * 256];      // fp32 [pi_f | pi_s] per node
// INTERLEAVED fp16 pj: per node 256 halves; lane l: halves [8l,8l+4) = f ch 4l..4l+3,
// halves [8l+4, 8l+8) = q ch 4l..4l+3.
__device__ __half g_Pj16[(size_t)NN * 256];
__device__ float  g_aggr[(size_t)NN * CC];     // segment-sum result
__device__ float  g_stats[2 * CC];             // per-channel sum, sumsq
__device__ __half g_Wcat16T[512 * 128];        // packed weights, TRANSPOSED [n][k], fp16
// CSR scratch
__device__ int    g_deg[NN];
__device__ int    g_roff[NN];
__device__ int    g_cursor[NN];
__device__ int    g_total;
__device__ int2   g_epack[EE];                 // (src, e-bits) grouped by dst row

__device__ __forceinline__ float sp_f(float x) {
    return x > 15.0f ? x : __logf(1.0f + __expf(x));
}
__device__ __forceinline__ float sigm_f(float x) {
    float t;
    asm("tanh.approx.f32 %0, %1;" : "=f"(t) : "f"(x * 0.5f));
    return fmaf(0.5f, t, 0.5f);
}

// ---------------- weight packing (fp16, transposed [n][k]) ----------------
__global__ void prep_wcat(const float* __restrict__ Wf, const float* __restrict__ Ws) {
    int idx = blockIdx.x * blockDim.x + threadIdx.x;   // n*128 + k
    if (idx >= 512 * 128) return;
    int n = idx >> 7;
    int k = idx & 127;
    float v;
    if (n < 128)      v = Wf[k * 128 + n];
    else if (n < 256) v = Ws[k * 128 + (n - 128)];
    else if (n < 384) v = Wf[(128 + k) * 128 + (n - 256)];
    else              v = Ws[(128 + k) * 128 + (n - 384)];
    g_Wcat16T[idx] = __float2half(v);
}

// ---------------- GEMM1 (fp32 SIMT): out = softplus(h@W0 + b0), + fp16 copy ----
__global__ void __launch_bounds__(256, 2)
gemm1(const float* __restrict__ A, const float* __restrict__ B,
      const float* __restrict__ bias, int M) {
    __shared__ float As[16][132];
    __shared__ float Bs[16][128];
    int tid = threadIdx.x;
    int tx = tid & 15, ty = tid >> 4;
    int row0 = blockIdx.x * 128;
    float acc[8][8] = {};

    for (int kc = 0; kc < KK; kc += 16) {
#pragma unroll
        for (int l = 0; l < 2; l++) {
            int f = tid + l * 256;
            int m = f >> 2;
            int kq = (f & 3) << 2;
            int gr = row0 + m;
            float4 av = make_float4(0.f, 0.f, 0.f, 0.f);
            if (gr < M) av = *(const float4*)(A + (size_t)gr * KK + kc + kq);
            As[kq + 0][m] = av.x;
            As[kq + 1][m] = av.y;
            As[kq + 2][m] = av.z;
            As[kq + 3][m] = av.w;
        }
#pragma unroll
        for (int l = 0; l < 2; l++) {
            int f = tid + l * 256;
            int k = f >> 5;
            int c4 = (f & 31) << 2;
            *(float4*)&Bs[k][c4] = *(const float4*)(B + (size_t)(kc + k) * CC + c4);
        }
        __syncthreads();
#pragma unroll
        for (int k = 0; k < 16; k++) {
            float4 a0 = *(float4*)&As[k][ty * 4];
            float4 a1 = *(float4*)&As[k][64 + ty * 4];
            float4 b0 = *(float4*)&Bs[k][tx * 4];
            float4 b1 = *(float4*)&Bs[k][64 + tx * 4];
            float ar[8] = {a0.x, a0.y, a0.z, a0.w, a1.x, a1.y, a1.z, a1.w};
            float br[8] = {b0.x, b0.y, b0.z, b0.w, b1.x, b1.y, b1.z, b1.w};
#pragma unroll
            for (int i = 0; i < 8; i++)
#pragma unroll
                for (int j = 0; j < 8; j++)
                    acc[i][j] += ar[i] * br[j];
        }
        __syncthreads();
    }

#pragma unroll
    for (int i = 0; i < 8; i++) {
        int gr = row0 + (i < 4 ? ty * 4 + i : 64 + ty * 4 + (i - 4));
        if (gr >= M) continue;
#pragma unroll
        for (int half = 0; half < 2; half++) {
            int gc = half * 64 + tx * 4;
            float4 v;
            v.x = sp_f(acc[i][half * 4 + 0] + bias[gc + 0]);
            v.y = sp_f(acc[i][half * 4 + 1] + bias[gc + 1]);
            v.z = sp_f(acc[i][half * 4 + 2] + bias[gc + 2]);
            v.w = sp_f(acc[i][half * 4 + 3] + bias[gc + 3]);
            *(float4*)(g_out + (size_t)gr * CC + gc) = v;
            __half2 h0 = __floats2half2_rn(v.x, v.y);
            __half2 h1 = __floats2half2_rn(v.z, v.w);
            uint2 u;
            u.x = *(unsigned*)&h0;
            u.y = *(unsigned*)&h1;
            *(uint2*)(g_out16 + (size_t)gr * CC + gc) = u;
        }
    }
}

// ---------------- GEMM2 (fp16 tensor core): P = out @ Wcat ----------------
// nblk 0,1 -> g_Pi fp32; nblk 2 -> Pj f-slots; nblk 3 -> Pj q-slots (interleaved).
__global__ void __launch_bounds__(256, 2)
gemm2_tc() {
    extern __shared__ __half smemh[];
    __half* As = smemh;                 // [128][LDH]
    __half* Bs = smemh + 128 * LDH;     // [128][LDH], row n, col k
    int tid = threadIdx.x;
    int row0 = blockIdx.x * 128;
    int nblk = blockIdx.y;

#pragma unroll
    for (int l = 0; l < 8; l++) {
        int idx = tid + l * 256;
        int r = idx >> 4;
        int c8 = (idx & 15) << 3;
        int4 v = make_int4(0, 0, 0, 0);
        int gr = row0 + r;
        if (gr < NN) v = *(const int4*)(g_out16 + (size_t)gr * CC + c8);
        *(int4*)(As + r * LDH + c8) = v;
        int4 w = *(const int4*)(g_Wcat16T + ((size_t)(nblk * 128 + r)) * CC + c8);
        *(int4*)(Bs + r * LDH + c8) = w;
    }
    __syncthreads();

    int lane = tid & 31;
    int w = tid >> 5;
    int g = lane >> 2, tig = lane & 3;
    int wm = (w & 1) * 64, wn = (w >> 1) * 32;

    float acc[4][4][4];
#pragma unroll
    for (int mt = 0; mt < 4; mt++)
#pragma unroll
        for (int nt = 0; nt < 4; nt++)
#pragma unroll
            for (int q = 0; q < 4; q++) acc[mt][nt][q] = 0.f;

    const unsigned* As2 = (const unsigned*)As;
    const unsigned* Bs2 = (const unsigned*)Bs;

#pragma unroll
    for (int ks = 0; ks < 8; ks++) {
        int kk = ks * 8;
        unsigned a[4][4], b[4][2];
#pragma unroll
        for (int mt = 0; mt < 4; mt++) {
            int r = wm + mt * 16 + g;
            a[mt][0] = As2[r * 68 + kk + tig];
            a[mt][1] = As2[(r + 8) * 68 + kk + tig];
            a[mt][2] = As2[r * 68 + kk + 4 + tig];
            a[mt][3] = As2[(r + 8) * 68 + kk + 4 + tig];
        }
#pragma unroll
        for (int nt = 0; nt < 4; nt++) {
            int r = wn + nt * 8 + g;
            b[nt][0] = Bs2[r * 68 + kk + tig];
            b[nt][1] = Bs2[r * 68 + kk + 4 + tig];
        }
#pragma unroll
        for (int mt = 0; mt < 4; mt++)
#pragma unroll
            for (int nt = 0; nt < 4; nt++) {
                asm volatile(
                    "mma.sync.aligned.m16n8k16.row.col.f32.f16.f16.f32 "
                    "{%0,%1,%2,%3}, {%4,%5,%6,%7}, {%8,%9}, {%0,%1,%2,%3};"
                    : "+f"(acc[mt][nt][0]), "+f"(acc[mt][nt][1]),
                      "+f"(acc[mt][nt][2]), "+f"(acc[mt][nt][3])
                    : "r"(a[mt][0]), "r"(a[mt][1]), "r"(a[mt][2]), "r"(a[mt][3]),
                      "r"(b[nt][0]), "r"(b[nt][1]));
            }
    }

#pragma unroll
    for (int mt = 0; mt < 4; mt++) {
#pragma unroll
        for (int nt = 0; nt < 4; nt++) {
            int gr0 = row0 + wm + mt * 16 + g;
            int gr1 = gr0 + 8;
            float d0 = acc[mt][nt][0], d1 = acc[mt][nt][1];
            float d2 = acc[mt][nt][2], d3 = acc[mt][nt][3];
            if (nblk < 2) {
                int col = nblk * 128 + wn + nt * 8 + tig * 2;
                if (gr0 < NN) *(float2*)(g_Pi + (size_t)gr0 * 256 + col) = make_float2(d0, d1);
                if (gr1 < NN) *(float2*)(g_Pi + (size_t)gr1 * 256 + col) = make_float2(d2, d3);
            } else {
                int c0 = wn + nt * 8 + tig * 2;                 // channel 0..127 (even)
                int hoff = ((c0 >> 2) << 3) + (c0 & 3) + (nblk == 3 ? 4 : 0);
                __half2 h01 = __floats2half2_rn(d0, d1);
                __half2 h23 = __floats2half2_rn(d2, d3);
                if (gr0 < NN) *(unsigned*)(g_Pj16 + (size_t)gr0 * 256 + hoff) = *(unsigned*)&h01;
                if (gr1 < NN) *(unsigned*)(g_Pj16 + (size_t)gr1 * 256 + hoff) = *(unsigned*)&h23;
            }
        }
    }
}

// ---------------- CSR build ----------------
__global__ void hist(const int* __restrict__ ei) {
    int e = blockIdx.x * blockDim.x + threadIdx.x;
    if (e < EE) atomicAdd(&g_deg[ei[EE + e]], 1);
}

// Row offsets via global atomic (order-free CSR; warp-aggregated by ptxas)
__global__ void assign_off() {
    int i = blockIdx.x * blockDim.x + threadIdx.x;
    if (i < NN) {
        int d = g_deg[i];
        int r = atomicAdd(&g_total, d);
        g_roff[i] = r;
        g_cursor[i] = r;
    }
}

// ---------------- e = softplus(edge_attr @ Wsh + bsh) fused with CSR scatter
__global__ void edge_gauss_scatter(const float* __restrict__ ea,
                                   const float* __restrict__ Wsh,
                                   const float* __restrict__ bsh,
                                   const int* __restrict__ ei) {
    int t = blockIdx.x * blockDim.x + threadIdx.x;
    int e = t >> 3;
    if (e >= EE) return;
    int l = t & 7;
    const float4* base = (const float4*)(ea + (size_t)e * 128) + l * 4;
    const float4* wb = (const float4*)Wsh + l * 4;
    float4 a0 = base[0], a1 = base[1], a2 = base[2], a3 = base[3];
    float4 w0 = wb[0], w1 = wb[1], w2 = wb[2], w3 = wb[3];
    float d = a0.x * w0.x + a0.y * w0.y + a0.z * w0.z + a0.w * w0.w
            + a1.x * w1.x + a1.y * w1.y + a1.z * w1.z + a1.w * w1.w
            + a2.x * w2.x + a2.y * w2.y + a2.z * w2.z + a2.w * w2.w
            + a3.x * w3.x + a3.y * w3.y + a3.z * w3.z + a3.w * w3.w;
#pragma unroll
    for (int o = 4; o; o >>= 1) d += __shfl_xor_sync(0xFFFFFFFFu, d, o);
    if (l == 0) {
        float ev = sp_f(d + bsh[0]);
        int src = __ldg(ei + e);
        int dst = __ldg(ei + EE + e);
        int pos = atomicAdd(&g_cursor[dst], 1);
        g_epack[pos] = make_int2(src, __float_as_int(ev));
    }
}

// ---------------- CSR edge messages + fused BN stats ----------------
// Interleaved pj: ONE uint4 per edge per lane (f|q for this lane's 4 channels).
__device__ __forceinline__ void pj_load(int src, int lane, float4& f, float4& q) {
    uint4 v = *(const uint4*)(g_Pj16 + (size_t)src * 256 + lane * 8);
    float2 f01 = __half22float2(*(__half2*)&v.x);
    float2 f23 = __half22float2(*(__half2*)&v.y);
    float2 q01 = __half22float2(*(__half2*)&v.z);
    float2 q23 = __half22float2(*(__half2*)&v.w);
    f = make_float4(f01.x, f01.y, f23.x, f23.y);
    q = make_float4(q01.x, q01.y, q23.x, q23.y);
}

__device__ __forceinline__ void msg_add(float4& acc, const float4& pif, const float4& pis,
                                        const float4& f, const float4& q, float ev,
                                        const float4& wfe, const float4& wse) {
    acc.x += sigm_f(pif.x + f.x + ev * wfe.x) * sp_f(pis.x + q.x + ev * wse.x);
    acc.y += sigm_f(pif.y + f.y + ev * wfe.y) * sp_f(pis.y + q.y + ev * wse.y);
    acc.z += sigm_f(pif.z + f.z + ev * wfe.z) * sp_f(pis.z + q.z + ev * wse.z);
    acc.w += sigm_f(pif.w + f.w + ev * wfe.w) * sp_f(pis.w + q.w + ev * wse.w);
}

__global__ void __launch_bounds__(256)
edge_msg_csr(const float* __restrict__ Wf, const float* __restrict__ Ws,
             const float* __restrict__ bf, const float* __restrict__ bs,
             int nwarps) {
    __shared__ float s_stats[2 * CC];
    int tid = threadIdx.x;
    int lane = tid & 31;
    int c = lane * 4;
    s_stats[tid] = 0.0f;
    __syncthreads();

    float4 wfe = *(const float4*)(Wf + 256 * 128 + c);
    float4 wse = *(const float4*)(Ws + 256 * 128 + c);
    float4 bfv = *(const float4*)(bf + c);
    float4 bsv = *(const float4*)(bs + c);

    float lsum[4] = {}, lsq[4] = {};

    int gw = blockIdx.x * 8 + (tid >> 5);
    for (int i = gw; i < NN; i += nwarps) {
        const float4* Pi = (const float4*)(g_Pi + (size_t)i * 256);
        float4 pif = Pi[lane];
        float4 pis = Pi[32 + lane];
        pif.x += bfv.x; pif.y += bfv.y; pif.z += bfv.z; pif.w += bfv.w;
        pis.x += bsv.x; pis.y += bsv.y; pis.z += bsv.z; pis.w += bsv.w;
        int k = g_roff[i];
        int end = g_cursor[i];
        float4 acc = make_float4(0.f, 0.f, 0.f, 0.f);

        for (; k + 4 <= end; k += 4) {
            int2 p0 = g_epack[k], p1 = g_epack[k + 1];
            int2 p2 = g_epack[k + 2], p3 = g_epack[k + 3];
            float4 f0, q0, f1, q1, f2, q2, f3, q3;
            pj_load(p0.x, lane, f0, q0);
            pj_load(p1.x, lane, f1, q1);
            pj_load(p2.x, lane, f2, q2);
            pj_load(p3.x, lane, f3, q3);
            msg_add(acc, pif, pis, f0, q0, __int_as_float(p0.y), wfe, wse);
            msg_add(acc, pif, pis, f1, q1, __int_as_float(p1.y), wfe, wse);
            msg_add(acc, pif, pis, f2, q2, __int_as_float(p2.y), wfe, wse);
            msg_add(acc, pif, pis, f3, q3, __int_as_float(p3.y), wfe, wse);
        }
        for (; k < end; k++) {
            int2 p0 = g_epack[k];
            float4 f0, q0;
            pj_load(p0.x, lane, f0, q0);
            msg_add(acc, pif, pis, f0, q0, __int_as_float(p0.y), wfe, wse);
        }
        *(float4*)(g_aggr + (size_t)i * CC + c) = acc;
        lsum[0] += acc.x; lsum[1] += acc.y; lsum[2] += acc.z; lsum[3] += acc.w;
        lsq[0] += acc.x * acc.x; lsq[1] += acc.y * acc.y; lsq[2] += acc.z * acc.z; lsq[3] += acc.w * acc.w;
    }

#pragma unroll
    for (int j = 0; j < 4; j++) {
        atomicAdd(&s_stats[c + j], lsum[j]);
        atomicAdd(&s_stats[CC + c + j], lsq[j]);
    }
    __syncthreads();
    if (tid < 64) {
        float4 v = *(float4*)&s_stats[tid * 4];
        float* dstp = g_stats + tid * 4;
        asm volatile("red.global.add.v4.f32 [%0], {%1, %2, %3, %4};"
                     :: "l"(dstp), "f"(v.x), "f"(v.y), "f"(v.z), "f"(v.w)
                     : "memory");
    }
}

// ---------------- out_final = 2*out + batchnorm(aggr) ----------------
__global__ void finalize(const float* __restrict__ gamma, const float* __restrict__ beta,
                         float* __restrict__ out) {
    int i4 = blockIdx.x * blockDim.x + threadIdx.x;
    if (i4 >= NN * 32) return;
    int c = (i4 & 31) * 4;
    float4 a = *(const float4*)(g_aggr + (size_t)i4 * 4);
    float4 o = *(const float4*)(g_out + (size_t)i4 * 4);
    const float inv = 1.0f / NN;
    float4 r;
#pragma unroll
    for (int j = 0; j < 4; j++) {
        float sum = g_stats[c + j];
        float sq = g_stats[CC + c + j];
        float mean = sum * inv;
        float var = sq * inv - mean * mean;
        float scale = rsqrtf(var + 1e-5f) * gamma[c + j];
        float av = (&a.x)[j];
        float ov = (&o.x)[j];
        (&r.x)[j] = 2.0f * ov + (av - mean) * scale + beta[c + j];
    }
    *(float4*)(out + (size_t)i4 * 4) = r;
}

extern "C" void kernel_launch(void* const* d_in, const int* in_sizes, int n_in,
                              void* d_out, int out_size) {
    const float* h    = (const float*)d_in[0];
    const int*   ei   = (const int*)d_in[1];
    const float* ea   = (const float*)d_in[3];
    const float* W0   = (const float*)d_in[4];
    const float* b0   = (const float*)d_in[5];
    const float* Wsh  = (const float*)d_in[6];
    const float* bsh  = (const float*)d_in[7];
    const float* Wf   = (const float*)d_in[8];
    const float* bf   = (const float*)d_in[9];
    const float* Ws   = (const float*)d_in[10];
    const float* bs   = (const float*)d_in[11];
    const float* gamma = (const float*)d_in[12];
    const float* beta  = (const float*)d_in[13];
    float* out = (float*)d_out;

    float *p_stats;
    int *p_deg, *p_total;
    cudaGetSymbolAddress((void**)&p_stats, g_stats);
    cudaGetSymbolAddress((void**)&p_deg, g_deg);
    cudaGetSymbolAddress((void**)&p_total, g_total);

    static cudaStream_t s2 = nullptr;
    static cudaEvent_t evFork = nullptr, evJoin = nullptr;
    static bool attrSet = false;
    if (!s2) {
        cudaStreamCreateWithFlags(&s2, cudaStreamNonBlocking);
        cudaEventCreateWithFlags(&evFork, cudaEventDisableTiming);
        cudaEventCreateWithFlags(&evJoin, cudaEventDisableTiming);
    }
    if (!attrSet) {
        cudaFuncSetAttribute(gemm2_tc, cudaFuncAttributeMaxDynamicSharedMemorySize,
                             2 * 128 * LDH * (int)sizeof(__half));
        attrSet = true;
    }

    // ---- fork: edge/CSR pipeline on s2, node/GEMM pipeline on default ----
    cudaEventRecord(evFork, 0);
    cudaStreamWaitEvent(s2, evFork, 0);

    cudaMemsetAsync(p_deg, 0, NN * sizeof(int), s2);
    cudaMemsetAsync(p_total, 0, sizeof(int), s2);
    hist<<<(EE + 255) / 256, 256, 0, s2>>>(ei);
    assign_off<<<(NN + 255) / 256, 256, 0, s2>>>();
    edge_gauss_scatter<<<(EE * 8 + 255) / 256, 256, 0, s2>>>(ea, Wsh, bsh, ei);
    cudaEventRecord(evJoin, s2);

    cudaMemsetAsync(p_stats, 0, 2 * CC * sizeof(float));
    prep_wcat<<<(512 * 128 + 255) / 256, 256>>>(Wf, Ws);
    gemm1<<<(NN + 127) / 128, 256>>>(h, W0, b0, NN);
    gemm2_tc<<<dim3((NN + 127) / 128, 4), 256, 2 * 128 * LDH * sizeof(__half)>>>();

    cudaStreamWaitEvent(0, evJoin, 0);

    const int blocks = 1024;
    edge_msg_csr<<<blocks, 256>>>(Wf, Ws, bf, bs, blocks * 8);
    finalize<<<(NN * 32 + 255) / 256, 256>>>(gamma, beta, out);
}

// round 10
// speedup vs baseline: 1.0219x; 1.0189x over previous
#include <cuda_runtime.h>
#include <cuda_fp16.h>
#include <math.h>

#define NN 50000
#define EE 600000
#define CC 128
#define KK 128
#define LDH 136                           // padded smem row, halves

// Scratch (static device globals; no runtime allocation allowed)
__device__ float  g_out[(size_t)NN * CC];      // softplus(h@W0+b0) fp32
__device__ __half g_out16[(size_t)NN * CC];    // fp16 copy (A of TC GEMM)
__device__ float  g_Pi[(size_t)NN * 256];      // fp32 [pi_f | pi_s] per node
// INTERLEAVED fp16 pj: lane l: halves [8l,8l+4) = f ch 4l..4l+3, [8l+4,8l+8) = q.
__device__ __half g_Pj16[(size_t)NN * 256];
__device__ float  g_aggr[(size_t)NN * CC];     // segment-sum result
__device__ float  g_stats[2 * CC];             // per-channel sum, sumsq
__device__ __half g_Wcat16T[512 * 128];        // packed weights, TRANSPOSED [n][k], fp16
// CSR scratch
__device__ int    g_deg[NN];
__device__ int    g_roff[NN];
__device__ int    g_cursor[NN];
__device__ int    g_total;
__device__ int    g_ticket;                    // work-steal counter for edge_msg
__device__ int2   g_epack[EE];                 // (src, e-bits) grouped by dst row

__device__ __forceinline__ float sp_f(float x) {
    return x > 15.0f ? x : __logf(1.0f + __expf(x));
}
__device__ __forceinline__ float sigm_f(float x) {
    float t;
    asm("tanh.approx.f32 %0, %1;" : "=f"(t) : "f"(x * 0.5f));
    return fmaf(0.5f, t, 0.5f);
}

// ---------------- weight packing (fp16, transposed [n][k]) ----------------
__global__ void prep_wcat(const float* __restrict__ Wf, const float* __restrict__ Ws) {
    int idx = blockIdx.x * blockDim.x + threadIdx.x;   // n*128 + k
    if (idx >= 512 * 128) return;
    int n = idx >> 7;
    int k = idx & 127;
    float v;
    if (n < 128)      v = Wf[k * 128 + n];
    else if (n < 256) v = Ws[k * 128 + (n - 128)];
    else if (n < 384) v = Wf[(128 + k) * 128 + (n - 256)];
    else              v = Ws[(128 + k) * 128 + (n - 384)];
    g_Wcat16T[idx] = __float2half(v);
}

// ---------------- GEMM1 (fp32 SIMT): out = softplus(h@W0 + b0), + fp16 copy ----
__global__ void __launch_bounds__(256, 2)
gemm1(const float* __restrict__ A, const float* __restrict__ B,
      const float* __restrict__ bias, int M) {
    __shared__ float As[16][132];
    __shared__ float Bs[16][128];
    int tid = threadIdx.x;
    int tx = tid & 15, ty = tid >> 4;
    int row0 = blockIdx.x * 128;
    float acc[8][8] = {};

    for (int kc = 0; kc < KK; kc += 16) {
#pragma unroll
        for (int l = 0; l < 2; l++) {
            int f = tid + l * 256;
            int m = f >> 2;
            int kq = (f & 3) << 2;
            int gr = row0 + m;
            float4 av = make_float4(0.f, 0.f, 0.f, 0.f);
            if (gr < M) av = *(const float4*)(A + (size_t)gr * KK + kc + kq);
            As[kq + 0][m] = av.x;
            As[kq + 1][m] = av.y;
            As[kq + 2][m] = av.z;
            As[kq + 3][m] = av.w;
        }
#pragma unroll
        for (int l = 0; l < 2; l++) {
            int f = tid + l * 256;
            int k = f >> 5;
            int c4 = (f & 31) << 2;
            *(float4*)&Bs[k][c4] = *(const float4*)(B + (size_t)(kc + k) * CC + c4);
        }
        __syncthreads();
#pragma unroll
        for (int k = 0; k < 16; k++) {
            float4 a0 = *(float4*)&As[k][ty * 4];
            float4 a1 = *(float4*)&As[k][64 + ty * 4];
            float4 b0 = *(float4*)&Bs[k][tx * 4];
            float4 b1 = *(float4*)&Bs[k][64 + tx * 4];
            float ar[8] = {a0.x, a0.y, a0.z, a0.w, a1.x, a1.y, a1.z, a1.w};
            float br[8] = {b0.x, b0.y, b0.z, b0.w, b1.x, b1.y, b1.z, b1.w};
#pragma unroll
            for (int i = 0; i < 8; i++)
#pragma unroll
                for (int j = 0; j < 8; j++)
                    acc[i][j] += ar[i] * br[j];
        }
        __syncthreads();
    }

#pragma unroll
    for (int i = 0; i < 8; i++) {
        int gr = row0 + (i < 4 ? ty * 4 + i : 64 + ty * 4 + (i - 4));
        if (gr >= M) continue;
#pragma unroll
        for (int half = 0; half < 2; half++) {
            int gc = half * 64 + tx * 4;
            float4 v;
            v.x = sp_f(acc[i][half * 4 + 0] + bias[gc + 0]);
            v.y = sp_f(acc[i][half * 4 + 1] + bias[gc + 1]);
            v.z = sp_f(acc[i][half * 4 + 2] + bias[gc + 2]);
            v.w = sp_f(acc[i][half * 4 + 3] + bias[gc + 3]);
            *(float4*)(g_out + (size_t)gr * CC + gc) = v;
            __half2 h0 = __floats2half2_rn(v.x, v.y);
            __half2 h1 = __floats2half2_rn(v.z, v.w);
            uint2 u;
            u.x = *(unsigned*)&h0;
            u.y = *(unsigned*)&h1;
            *(uint2*)(g_out16 + (size_t)gr * CC + gc) = u;
        }
    }
}

// ---------------- GEMM2 (fp16 tensor core): P = out @ Wcat ----------------
__global__ void __launch_bounds__(256, 2)
gemm2_tc() {
    extern __shared__ __half smemh[];
    __half* As = smemh;                 // [128][LDH]
    __half* Bs = smemh + 128 * LDH;     // [128][LDH], row n, col k
    int tid = threadIdx.x;
    int row0 = blockIdx.x * 128;
    int nblk = blockIdx.y;

#pragma unroll
    for (int l = 0; l < 8; l++) {
        int idx = tid + l * 256;
        int r = idx >> 4;
        int c8 = (idx & 15) << 3;
        int4 v = make_int4(0, 0, 0, 0);
        int gr = row0 + r;
        if (gr < NN) v = *(const int4*)(g_out16 + (size_t)gr * CC + c8);
        *(int4*)(As + r * LDH + c8) = v;
        int4 w = *(const int4*)(g_Wcat16T + ((size_t)(nblk * 128 + r)) * CC + c8);
        *(int4*)(Bs + r * LDH + c8) = w;
    }
    __syncthreads();

    int lane = tid & 31;
    int w = tid >> 5;
    int g = lane >> 2, tig = lane & 3;
    int wm = (w & 1) * 64, wn = (w >> 1) * 32;

    float acc[4][4][4];
#pragma unroll
    for (int mt = 0; mt < 4; mt++)
#pragma unroll
        for (int nt = 0; nt < 4; nt++)
#pragma unroll
            for (int q = 0; q < 4; q++) acc[mt][nt][q] = 0.f;

    const unsigned* As2 = (const unsigned*)As;
    const unsigned* Bs2 = (const unsigned*)Bs;

#pragma unroll
    for (int ks = 0; ks < 8; ks++) {
        int kk = ks * 8;
        unsigned a[4][4], b[4][2];
#pragma unroll
        for (int mt = 0; mt < 4; mt++) {
            int r = wm + mt * 16 + g;
            a[mt][0] = As2[r * 68 + kk + tig];
            a[mt][1] = As2[(r + 8) * 68 + kk + tig];
            a[mt][2] = As2[r * 68 + kk + 4 + tig];
            a[mt][3] = As2[(r + 8) * 68 + kk + 4 + tig];
        }
#pragma unroll
        for (int nt = 0; nt < 4; nt++) {
            int r = wn + nt * 8 + g;
            b[nt][0] = Bs2[r * 68 + kk + tig];
            b[nt][1] = Bs2[r * 68 + kk + 4 + tig];
        }
#pragma unroll
        for (int mt = 0; mt < 4; mt++)
#pragma unroll
            for (int nt = 0; nt < 4; nt++) {
                asm volatile(
                    "mma.sync.aligned.m16n8k16.row.col.f32.f16.f16.f32 "
                    "{%0,%1,%2,%3}, {%4,%5,%6,%7}, {%8,%9}, {%0,%1,%2,%3};"
                    : "+f"(acc[mt][nt][0]), "+f"(acc[mt][nt][1]),
                      "+f"(acc[mt][nt][2]), "+f"(acc[mt][nt][3])
                    : "r"(a[mt][0]), "r"(a[mt][1]), "r"(a[mt][2]), "r"(a[mt][3]),
                      "r"(b[nt][0]), "r"(b[nt][1]));
            }
    }

#pragma unroll
    for (int mt = 0; mt < 4; mt++) {
#pragma unroll
        for (int nt = 0; nt < 4; nt++) {
            int gr0 = row0 + wm + mt * 16 + g;
            int gr1 = gr0 + 8;
            float d0 = acc[mt][nt][0], d1 = acc[mt][nt][1];
            float d2 = acc[mt][nt][2], d3 = acc[mt][nt][3];
            if (nblk < 2) {
                int col = nblk * 128 + wn + nt * 8 + tig * 2;
                if (gr0 < NN) *(float2*)(g_Pi + (size_t)gr0 * 256 + col) = make_float2(d0, d1);
                if (gr1 < NN) *(float2*)(g_Pi + (size_t)gr1 * 256 + col) = make_float2(d2, d3);
            } else {
                int c0 = wn + nt * 8 + tig * 2;                 // channel 0..127 (even)
                int hoff = ((c0 >> 2) << 3) + (c0 & 3) + (nblk == 3 ? 4 : 0);
                __half2 h01 = __floats2half2_rn(d0, d1);
                __half2 h23 = __floats2half2_rn(d2, d3);
                if (gr0 < NN) *(unsigned*)(g_Pj16 + (size_t)gr0 * 256 + hoff) = *(unsigned*)&h01;
                if (gr1 < NN) *(unsigned*)(g_Pj16 + (size_t)gr1 * 256 + hoff) = *(unsigned*)&h23;
            }
        }
    }
}

// ---------------- CSR build ----------------
__global__ void hist(const int* __restrict__ ei) {
    int e = blockIdx.x * blockDim.x + threadIdx.x;
    if (e < EE) atomicAdd(&g_deg[ei[EE + e]], 1);
}

__global__ void assign_off() {
    int i = blockIdx.x * blockDim.x + threadIdx.x;
    if (i < NN) {
        int d = g_deg[i];
        int r = atomicAdd(&g_total, d);
        g_roff[i] = r;
        g_cursor[i] = r;
    }
}

// ---------------- e = softplus(edge_attr @ Wsh + bsh) fused with CSR scatter
__global__ void edge_gauss_scatter(const float* __restrict__ ea,
                                   const float* __restrict__ Wsh,
                                   const float* __restrict__ bsh,
                                   const int* __restrict__ ei) {
    int t = blockIdx.x * blockDim.x + threadIdx.x;
    int e = t >> 3;
    if (e >= EE) return;
    int l = t & 7;
    const float4* base = (const float4*)(ea + (size_t)e * 128) + l * 4;
    const float4* wb = (const float4*)Wsh + l * 4;
    float4 a0 = base[0], a1 = base[1], a2 = base[2], a3 = base[3];
    float4 w0 = wb[0], w1 = wb[1], w2 = wb[2], w3 = wb[3];
    float d = a0.x * w0.x + a0.y * w0.y + a0.z * w0.z + a0.w * w0.w
            + a1.x * w1.x + a1.y * w1.y + a1.z * w1.z + a1.w * w1.w
            + a2.x * w2.x + a2.y * w2.y + a2.z * w2.z + a2.w * w2.w
            + a3.x * w3.x + a3.y * w3.y + a3.z * w3.z + a3.w * w3.w;
#pragma unroll
    for (int o = 4; o; o >>= 1) d += __shfl_xor_sync(0xFFFFFFFFu, d, o);
    if (l == 0) {
        float ev = sp_f(d + bsh[0]);
        int src = __ldg(ei + e);
        int dst = __ldg(ei + EE + e);
        int pos = atomicAdd(&g_cursor[dst], 1);
        g_epack[pos] = make_int2(src, __float_as_int(ev));
    }
}

// ---------------- CSR edge messages + fused BN stats (work-stealing) ------
__device__ __forceinline__ void pj_load(int src, int lane, float4& f, float4& q) {
    uint4 v = *(const uint4*)(g_Pj16 + (size_t)src * 256 + lane * 8);
    float2 f01 = __half22float2(*(__half2*)&v.x);
    float2 f23 = __half22float2(*(__half2*)&v.y);
    float2 q01 = __half22float2(*(__half2*)&v.z);
    float2 q23 = __half22float2(*(__half2*)&v.w);
    f = make_float4(f01.x, f01.y, f23.x, f23.y);
    q = make_float4(q01.x, q01.y, q23.x, q23.y);
}

__device__ __forceinline__ void msg_add(float4& acc, const float4& pif, const float4& pis,
                                        const float4& f, const float4& q, float ev,
                                        const float4& wfe, const float4& wse) {
    acc.x += sigm_f(pif.x + f.x + ev * wfe.x) * sp_f(pis.x + q.x + ev * wse.x);
    acc.y += sigm_f(pif.y + f.y + ev * wfe.y) * sp_f(pis.y + q.y + ev * wse.y);
    acc.z += sigm_f(pif.z + f.z + ev * wfe.z) * sp_f(pis.z + q.z + ev * wse.z);
    acc.w += sigm_f(pif.w + f.w + ev * wfe.w) * sp_f(pis.w + q.w + ev * wse.w);
}

__global__ void __launch_bounds__(256)
edge_msg_csr(const float* __restrict__ Wf, const float* __restrict__ Ws,
             const float* __restrict__ bf, const float* __restrict__ bs) {
    __shared__ float s_stats[2 * CC];
    int tid = threadIdx.x;
    int lane = tid & 31;
    int c = lane * 4;
    s_stats[tid] = 0.0f;
    __syncthreads();

    float4 wfe = *(const float4*)(Wf + 256 * 128 + c);
    float4 wse = *(const float4*)(Ws + 256 * 128 + c);
    float4 bfv = *(const float4*)(bf + c);
    float4 bsv = *(const float4*)(bs + c);

    float lsum[4] = {}, lsq[4] = {};

    // dynamic node assignment: lane 0 grabs tickets; next ticket prefetched
    int i = 0;
    if (lane == 0) i = atomicAdd(&g_ticket, 1);
    i = __shfl_sync(0xFFFFFFFFu, i, 0);

    while (i < NN) {
        int nexti = 0;
        if (lane == 0) nexti = atomicAdd(&g_ticket, 1);   // prefetch next ticket

        const float4* Pi = (const float4*)(g_Pi + (size_t)i * 256);
        float4 pif = Pi[lane];
        float4 pis = Pi[32 + lane];
        pif.x += bfv.x; pif.y += bfv.y; pif.z += bfv.z; pif.w += bfv.w;
        pis.x += bsv.x; pis.y += bsv.y; pis.z += bsv.z; pis.w += bsv.w;
        int k = g_roff[i];
        int end = g_cursor[i];
        float4 acc = make_float4(0.f, 0.f, 0.f, 0.f);

        for (; k + 4 <= end; k += 4) {
            int2 p0 = g_epack[k], p1 = g_epack[k + 1];
            int2 p2 = g_epack[k + 2], p3 = g_epack[k + 3];
            float4 f0, q0, f1, q1, f2, q2, f3, q3;
            pj_load(p0.x, lane, f0, q0);
            pj_load(p1.x, lane, f1, q1);
            pj_load(p2.x, lane, f2, q2);
            pj_load(p3.x, lane, f3, q3);
            msg_add(acc, pif, pis, f0, q0, __int_as_float(p0.y), wfe, wse);
            msg_add(acc, pif, pis, f1, q1, __int_as_float(p1.y), wfe, wse);
            msg_add(acc, pif, pis, f2, q2, __int_as_float(p2.y), wfe, wse);
            msg_add(acc, pif, pis, f3, q3, __int_as_float(p3.y), wfe, wse);
        }
        for (; k < end; k++) {
            int2 p0 = g_epack[k];
            float4 f0, q0;
            pj_load(p0.x, lane, f0, q0);
            msg_add(acc, pif, pis, f0, q0, __int_as_float(p0.y), wfe, wse);
        }
        *(float4*)(g_aggr + (size_t)i * CC + c) = acc;
        lsum[0] += acc.x; lsum[1] += acc.y; lsum[2] += acc.z; lsum[3] += acc.w;
        lsq[0] += acc.x * acc.x; lsq[1] += acc.y * acc.y; lsq[2] += acc.z * acc.z; lsq[3] += acc.w * acc.w;

        i = __shfl_sync(0xFFFFFFFFu, nexti, 0);
    }

#pragma unroll
    for (int j = 0; j < 4; j++) {
        atomicAdd(&s_stats[c + j], lsum[j]);
        atomicAdd(&s_stats[CC + c + j], lsq[j]);
    }
    __syncthreads();
    if (tid < 64) {
        float4 v = *(float4*)&s_stats[tid * 4];
        float* dstp = g_stats + tid * 4;
        asm volatile("red.global.add.v4.f32 [%0], {%1, %2, %3, %4};"
                     :: "l"(dstp), "f"(v.x), "f"(v.y), "f"(v.z), "f"(v.w)
                     : "memory");
    }
}

// ---------------- out_final = 2*out + batchnorm(aggr) ----------------
__global__ void finalize(const float* __restrict__ gamma, const float* __restrict__ beta,
                         float* __restrict__ out) {
    int i4 = blockIdx.x * blockDim.x + threadIdx.x;
    if (i4 >= NN * 32) return;
    int c = (i4 & 31) * 4;
    float4 a = *(const float4*)(g_aggr + (size_t)i4 * 4);
    float4 o = *(const float4*)(g_out + (size_t)i4 * 4);
    const float inv = 1.0f / NN;
    float4 r;
#pragma unroll
    for (int j = 0; j < 4; j++) {
        float sum = g_stats[c + j];
        float sq = g_stats[CC + c + j];
        float mean = sum * inv;
        float var = sq * inv - mean * mean;
        float scale = rsqrtf(var + 1e-5f) * gamma[c + j];
        float av = (&a.x)[j];
        float ov = (&o.x)[j];
        (&r.x)[j] = 2.0f * ov + (av - mean) * scale + beta[c + j];
    }
    *(float4*)(out + (size_t)i4 * 4) = r;
}

extern "C" void kernel_launch(void* const* d_in, const int* in_sizes, int n_in,
                              void* d_out, int out_size) {
    const float* h    = (const float*)d_in[0];
    const int*   ei   = (const int*)d_in[1];
    const float* ea   = (const float*)d_in[3];
    const float* W0   = (const float*)d_in[4];
    const float* b0   = (const float*)d_in[5];
    const float* Wsh  = (const float*)d_in[6];
    const float* bsh  = (const float*)d_in[7];
    const float* Wf   = (const float*)d_in[8];
    const float* bf   = (const float*)d_in[9];
    const float* Ws   = (const float*)d_in[10];
    const float* bs   = (const float*)d_in[11];
    const float* gamma = (const float*)d_in[12];
    const float* beta  = (const float*)d_in[13];
    float* out = (float*)d_out;

    float *p_stats;
    int *p_deg, *p_total, *p_ticket;
    cudaGetSymbolAddress((void**)&p_stats, g_stats);
    cudaGetSymbolAddress((void**)&p_deg, g_deg);
    cudaGetSymbolAddress((void**)&p_total, g_total);
    cudaGetSymbolAddress((void**)&p_ticket, g_ticket);

    static cudaStream_t s2 = nullptr;
    static cudaEvent_t evFork = nullptr, evJoin = nullptr;
    static bool attrSet = false;
    if (!s2) {
        cudaStreamCreateWithFlags(&s2, cudaStreamNonBlocking);
        cudaEventCreateWithFlags(&evFork, cudaEventDisableTiming);
        cudaEventCreateWithFlags(&evJoin, cudaEventDisableTiming);
    }
    if (!attrSet) {
        cudaFuncSetAttribute(gemm2_tc, cudaFuncAttributeMaxDynamicSharedMemorySize,
                             2 * 128 * LDH * (int)sizeof(__half));
        attrSet = true;
    }

    // ---- fork: edge/CSR pipeline on s2, node/GEMM pipeline on default ----
    cudaEventRecord(evFork, 0);
    cudaStreamWaitEvent(s2, evFork, 0);

    cudaMemsetAsync(p_deg, 0, NN * sizeof(int), s2);
    cudaMemsetAsync(p_total, 0, sizeof(int), s2);
    hist<<<(EE + 255) / 256, 256, 0, s2>>>(ei);
    assign_off<<<(NN + 255) / 256, 256, 0, s2>>>();
    edge_gauss_scatter<<<(EE * 8 + 255) / 256, 256, 0, s2>>>(ea, Wsh, bsh, ei);
    cudaEventRecord(evJoin, s2);

    cudaMemsetAsync(p_stats, 0, 2 * CC * sizeof(float));
    cudaMemsetAsync(p_ticket, 0, sizeof(int));
    prep_wcat<<<(512 * 128 + 255) / 256, 256>>>(Wf, Ws);
    gemm1<<<(NN + 127) / 128, 256>>>(h, W0, b0, NN);
    gemm2_tc<<<dim3((NN + 127) / 128, 4), 256, 2 * 128 * LDH * sizeof(__half)>>>();

    cudaStreamWaitEvent(0, evJoin, 0);

    edge_msg_csr<<<1024, 256>>>(Wf, Ws, bf, bs);
    finalize<<<(NN * 32 + 255) / 256, 256>>>(gamma, beta, out);
}

// round 12
// speedup vs baseline: 1.0635x; 1.0407x over previous
#include <cuda_runtime.h>
#include <cuda_fp16.h>
#include <math.h>

#define NN 50000
#define EE 600000
#define CC 128
#define KK 128
#define LDH 136                           // padded smem row, halves

// Scratch (static device globals; no runtime allocation allowed)
__device__ float  g_out[(size_t)NN * CC];      // softplus(h@W0+b0) fp32
__device__ __half g_out16[(size_t)NN * CC];    // fp16 copy (A of TC GEMM)
__device__ float  g_Pi[(size_t)NN * 256];      // fp32 [pi_f | pi_s] per node
// INTERLEAVED fp16 pj: lane l: halves [8l,8l+4) = f ch 4l..4l+3, [8l+4,8l+8) = q.
__device__ __half g_Pj16[(size_t)NN * 256];
__device__ float  g_aggr[(size_t)NN * CC];     // segment-sum result
__device__ float  g_stats[2 * CC];             // per-channel sum, sumsq
__device__ __half g_Wcat16T[512 * 128];        // packed weights, TRANSPOSED [n][k], fp16
// CSR scratch
__device__ int    g_deg[NN];
__device__ int    g_roff[NN];
__device__ int    g_cursor[NN];
__device__ int    g_total;
__device__ int    g_ticket;                    // work-steal counter for edge_msg
__device__ int2   g_epack[EE];                 // (src, e-bits) grouped by dst row

__device__ __forceinline__ float sp_f(float x) {
    return x > 15.0f ? x : __logf(1.0f + __expf(x));
}
__device__ __forceinline__ float sigm_f(float x) {
    float t;
    asm("tanh.approx.f32 %0, %1;" : "=f"(t) : "f"(x * 0.5f));
    return fmaf(0.5f, t, 0.5f);
}

// ---------------- weight packing (fp16, transposed [n][k]) ----------------
__global__ void prep_wcat(const float* __restrict__ Wf, const float* __restrict__ Ws) {
    int idx = blockIdx.x * blockDim.x + threadIdx.x;   // n*128 + k
    if (idx >= 512 * 128) return;
    int n = idx >> 7;
    int k = idx & 127;
    float v;
    if (n < 128)      v = Wf[k * 128 + n];
    else if (n < 256) v = Ws[k * 128 + (n - 128)];
    else if (n < 384) v = Wf[(128 + k) * 128 + (n - 256)];
    else              v = Ws[(128 + k) * 128 + (n - 384)];
    g_Wcat16T[idx] = __float2half(v);
}

// ---------------- GEMM1 (fp32 SIMT): out = softplus(h@W0 + b0), + fp16 copy ----
__global__ void __launch_bounds__(256, 2)
gemm1(const float* __restrict__ A, const float* __restrict__ B,
      const float* __restrict__ bias, int M) {
    __shared__ float As[16][132];
    __shared__ float Bs[16][128];
    int tid = threadIdx.x;
    int tx = tid & 15, ty = tid >> 4;
    int row0 = blockIdx.x * 128;
    float acc[8][8] = {};

    for (int kc = 0; kc < KK; kc += 16) {
#pragma unroll
        for (int l = 0; l < 2; l++) {
            int f = tid + l * 256;
            int m = f >> 2;
            int kq = (f & 3) << 2;
            int gr = row0 + m;
            float4 av = make_float4(0.f, 0.f, 0.f, 0.f);
            if (gr < M) av = *(const float4*)(A + (size_t)gr * KK + kc + kq);
            As[kq + 0][m] = av.x;
            As[kq + 1][m] = av.y;
            As[kq + 2][m] = av.z;
            As[kq + 3][m] = av.w;
        }
#pragma unroll
        for (int l = 0; l < 2; l++) {
            int f = tid + l * 256;
            int k = f >> 5;
            int c4 = (f & 31) << 2;
            *(float4*)&Bs[k][c4] = *(const float4*)(B + (size_t)(kc + k) * CC + c4);
        }
        __syncthreads();
#pragma unroll
        for (int k = 0; k < 16; k++) {
            float4 a0 = *(float4*)&As[k][ty * 4];
            float4 a1 = *(float4*)&As[k][64 + ty * 4];
            float4 b0 = *(float4*)&Bs[k][tx * 4];
            float4 b1 = *(float4*)&Bs[k][64 + tx * 4];
            float ar[8] = {a0.x, a0.y, a0.z, a0.w, a1.x, a1.y, a1.z, a1.w};
            float br[8] = {b0.x, b0.y, b0.z, b0.w, b1.x, b1.y, b1.z, b1.w};
#pragma unroll
            for (int i = 0; i < 8; i++)
#pragma unroll
                for (int j = 0; j < 8; j++)
                    acc[i][j] += ar[i] * br[j];
        }
        __syncthreads();
    }

#pragma unroll
    for (int i = 0; i < 8; i++) {
        int gr = row0 + (i < 4 ? ty * 4 + i : 64 + ty * 4 + (i - 4));
        if (gr >= M) continue;
#pragma unroll
        for (int half = 0; half < 2; half++) {
            int gc = half * 64 + tx * 4;
            float4 v;
            v.x = sp_f(acc[i][half * 4 + 0] + bias[gc + 0]);
            v.y = sp_f(acc[i][half * 4 + 1] + bias[gc + 1]);
            v.z = sp_f(acc[i][half * 4 + 2] + bias[gc + 2]);
            v.w = sp_f(acc[i][half * 4 + 3] + bias[gc + 3]);
            *(float4*)(g_out + (size_t)gr * CC + gc) = v;
            __half2 h0 = __floats2half2_rn(v.x, v.y);
            __half2 h1 = __floats2half2_rn(v.z, v.w);
            uint2 u;
            u.x = *(unsigned*)&h0;
            u.y = *(unsigned*)&h1;
            *(uint2*)(g_out16 + (size_t)gr * CC + gc) = u;
        }
    }
}

// ---------------- GEMM2 (fp16 tensor core): P = out @ Wcat ----------------
__global__ void __launch_bounds__(256, 2)
gemm2_tc() {
    extern __shared__ __half smemh[];
    __half* As = smemh;                 // [128][LDH]
    __half* Bs = smemh + 128 * LDH;     // [128][LDH], row n, col k
    int tid = threadIdx.x;
    int row0 = blockIdx.x * 128;
    int nblk = blockIdx.y;

#pragma unroll
    for (int l = 0; l < 8; l++) {
        int idx = tid + l * 256;
        int r = idx >> 4;
        int c8 = (idx & 15) << 3;
        int4 v = make_int4(0, 0, 0, 0);
        int gr = row0 + r;
        if (gr < NN) v = *(const int4*)(g_out16 + (size_t)gr * CC + c8);
        *(int4*)(As + r * LDH + c8) = v;
        int4 w = *(const int4*)(g_Wcat16T + ((size_t)(nblk * 128 + r)) * CC + c8);
        *(int4*)(Bs + r * LDH + c8) = w;
    }
    __syncthreads();

    int lane = tid & 31;
    int w = tid >> 5;
    int g = lane >> 2, tig = lane & 3;
    int wm = (w & 1) * 64, wn = (w >> 1) * 32;

    float acc[4][4][4];
#pragma unroll
    for (int mt = 0; mt < 4; mt++)
#pragma unroll
        for (int nt = 0; nt < 4; nt++)
#pragma unroll
            for (int q = 0; q < 4; q++) acc[mt][nt][q] = 0.f;

    const unsigned* As2 = (const unsigned*)As;
    const unsigned* Bs2 = (const unsigned*)Bs;

#pragma unroll
    for (int ks = 0; ks < 8; ks++) {
        int kk = ks * 8;
        unsigned a[4][4], b[4][2];
#pragma unroll
        for (int mt = 0; mt < 4; mt++) {
            int r = wm + mt * 16 + g;
            a[mt][0] = As2[r * 68 + kk + tig];
            a[mt][1] = As2[(r + 8) * 68 + kk + tig];
            a[mt][2] = As2[r * 68 + kk + 4 + tig];
            a[mt][3] = As2[(r + 8) * 68 + kk + 4 + tig];
        }
#pragma unroll
        for (int nt = 0; nt < 4; nt++) {
            int r = wn + nt * 8 + g;
            b[nt][0] = Bs2[r * 68 + kk + tig];
            b[nt][1] = Bs2[r * 68 + kk + 4 + tig];
        }
#pragma unroll
        for (int mt = 0; mt < 4; mt++)
#pragma unroll
            for (int nt = 0; nt < 4; nt++) {
                asm volatile(
                    "mma.sync.aligned.m16n8k16.row.col.f32.f16.f16.f32 "
                    "{%0,%1,%2,%3}, {%4,%5,%6,%7}, {%8,%9}, {%0,%1,%2,%3};"
                    : "+f"(acc[mt][nt][0]), "+f"(acc[mt][nt][1]),
                      "+f"(acc[mt][nt][2]), "+f"(acc[mt][nt][3])
                    : "r"(a[mt][0]), "r"(a[mt][1]), "r"(a[mt][2]), "r"(a[mt][3]),
                      "r"(b[nt][0]), "r"(b[nt][1]));
            }
    }

#pragma unroll
    for (int mt = 0; mt < 4; mt++) {
#pragma unroll
        for (int nt = 0; nt < 4; nt++) {
            int gr0 = row0 + wm + mt * 16 + g;
            int gr1 = gr0 + 8;
            float d0 = acc[mt][nt][0], d1 = acc[mt][nt][1];
            float d2 = acc[mt][nt][2], d3 = acc[mt][nt][3];
            if (nblk < 2) {
                int col = nblk * 128 + wn + nt * 8 + tig * 2;
                if (gr0 < NN) *(float2*)(g_Pi + (size_t)gr0 * 256 + col) = make_float2(d0, d1);
                if (gr1 < NN) *(float2*)(g_Pi + (size_t)gr1 * 256 + col) = make_float2(d2, d3);
            } else {
                int c0 = wn + nt * 8 + tig * 2;                 // channel 0..127 (even)
                int hoff = ((c0 >> 2) << 3) + (c0 & 3) + (nblk == 3 ? 4 : 0);
                __half2 h01 = __floats2half2_rn(d0, d1);
                __half2 h23 = __floats2half2_rn(d2, d3);
                if (gr0 < NN) *(unsigned*)(g_Pj16 + (size_t)gr0 * 256 + hoff) = *(unsigned*)&h01;
                if (gr1 < NN) *(unsigned*)(g_Pj16 + (size_t)gr1 * 256 + hoff) = *(unsigned*)&h23;
            }
        }
    }
}

// ---------------- CSR build ----------------
__global__ void hist(const int* __restrict__ ei) {
    int e = blockIdx.x * blockDim.x + threadIdx.x;
    if (e < EE) atomicAdd(&g_deg[ei[EE + e]], 1);
}

__global__ void assign_off() {
    int i = blockIdx.x * blockDim.x + threadIdx.x;
    if (i < NN) {
        int d = g_deg[i];
        int r = atomicAdd(&g_total, d);
        g_roff[i] = r;
        g_cursor[i] = r;
    }
}

// ---------------- e = softplus(edge_attr @ Wsh + bsh) fused with CSR scatter
__global__ void edge_gauss_scatter(const float* __restrict__ ea,
                                   const float* __restrict__ Wsh,
                                   const float* __restrict__ bsh,
                                   const int* __restrict__ ei) {
    int t = blockIdx.x * blockDim.x + threadIdx.x;
    int e = t >> 3;
    if (e >= EE) return;
    int l = t & 7;
    const float4* base = (const float4*)(ea + (size_t)e * 128) + l * 4;
    const float4* wb = (const float4*)Wsh + l * 4;
    float4 a0 = base[0], a1 = base[1], a2 = base[2], a3 = base[3];
    float4 w0 = wb[0], w1 = wb[1], w2 = wb[2], w3 = wb[3];
    float d = a0.x * w0.x + a0.y * w0.y + a0.z * w0.z + a0.w * w0.w
            + a1.x * w1.x + a1.y * w1.y + a1.z * w1.z + a1.w * w1.w
            + a2.x * w2.x + a2.y * w2.y + a2.z * w2.z + a2.w * w2.w
            + a3.x * w3.x + a3.y * w3.y + a3.z * w3.z + a3.w * w3.w;
#pragma unroll
    for (int o = 4; o; o >>= 1) d += __shfl_xor_sync(0xFFFFFFFFu, d, o);
    if (l == 0) {
        float ev = sp_f(d + bsh[0]);
        int src = __ldg(ei + e);
        int dst = __ldg(ei + EE + e);
        int pos = atomicAdd(&g_cursor[dst], 1);
        g_epack[pos] = make_int2(src, __float_as_int(ev));
    }
}

// ---------------- CSR edge messages + fused BN stats (work-stealing) ------
__device__ __forceinline__ void pj_load(int src, int lane, float4& f, float4& q) {
    uint4 v = *(const uint4*)(g_Pj16 + (size_t)src * 256 + lane * 8);
    float2 f01 = __half22float2(*(__half2*)&v.x);
    float2 f23 = __half22float2(*(__half2*)&v.y);
    float2 q01 = __half22float2(*(__half2*)&v.z);
    float2 q23 = __half22float2(*(__half2*)&v.w);
    f = make_float4(f01.x, f01.y, f23.x, f23.y);
    q = make_float4(q01.x, q01.y, q23.x, q23.y);
}

__device__ __forceinline__ void msg_add(float4& acc, const float4& pif, const float4& pis,
                                        const float4& f, const float4& q, float ev,
                                        const float4& wfe, const float4& wse) {
    acc.x += sigm_f(pif.x + f.x + ev * wfe.x) * sp_f(pis.x + q.x + ev * wse.x);
    acc.y += sigm_f(pif.y + f.y + ev * wfe.y) * sp_f(pis.y + q.y + ev * wse.y);
    acc.z += sigm_f(pif.z + f.z + ev * wfe.z) * sp_f(pis.z + q.z + ev * wse.z);
    acc.w += sigm_f(pif.w + f.w + ev * wfe.w) * sp_f(pis.w + q.w + ev * wse.w);
}

__global__ void __launch_bounds__(256)
edge_msg_csr(const float* __restrict__ Wf, const float* __restrict__ Ws,
             const float* __restrict__ bf, const float* __restrict__ bs) {
    __shared__ float s_stats[2 * CC];
    int tid = threadIdx.x;
    int lane = tid & 31;
    int c = lane * 4;
    s_stats[tid] = 0.0f;
    __syncthreads();

    float4 wfe = *(const float4*)(Wf + 256 * 128 + c);
    float4 wse = *(const float4*)(Ws + 256 * 128 + c);
    float4 bfv = *(const float4*)(bf + c);
    float4 bsv = *(const float4*)(bs + c);

    float lsum[4] = {}, lsq[4] = {};

    int i = 0;
    if (lane == 0) i = atomicAdd(&g_ticket, 1);
    i = __shfl_sync(0xFFFFFFFFu, i, 0);

    while (i < NN) {
        int nexti = 0;
        if (lane == 0) nexti = atomicAdd(&g_ticket, 1);   // prefetch next ticket

        const float4* Pi = (const float4*)(g_Pi + (size_t)i * 256);
        float4 pif = Pi[lane];
        float4 pis = Pi[32 + lane];
        pif.x += bfv.x; pif.y += bfv.y; pif.z += bfv.z; pif.w += bfv.w;
        pis.x += bsv.x; pis.y += bsv.y; pis.z += bsv.z; pis.w += bsv.w;
        int k = g_roff[i];
        int end = g_cursor[i];
        float4 acc = make_float4(0.f, 0.f, 0.f, 0.f);

        for (; k + 4 <= end; k += 4) {
            int2 p0 = g_epack[k], p1 = g_epack[k + 1];
            int2 p2 = g_epack[k + 2], p3 = g_epack[k + 3];
            float4 f0, q0, f1, q1, f2, q2, f3, q3;
            pj_load(p0.x, lane, f0, q0);
            pj_load(p1.x, lane, f1, q1);
            pj_load(p2.x, lane, f2, q2);
            pj_load(p3.x, lane, f3, q3);
            msg_add(acc, pif, pis, f0, q0, __int_as_float(p0.y), wfe, wse);
            msg_add(acc, pif, pis, f1, q1, __int_as_float(p1.y), wfe, wse);
            msg_add(acc, pif, pis, f2, q2, __int_as_float(p2.y), wfe, wse);
            msg_add(acc, pif, pis, f3, q3, __int_as_float(p3.y), wfe, wse);
        }
        for (; k < end; k++) {
            int2 p0 = g_epack[k];
            float4 f0, q0;
            pj_load(p0.x, lane, f0, q0);
            msg_add(acc, pif, pis, f0, q0, __int_as_float(p0.y), wfe, wse);
        }
        *(float4*)(g_aggr + (size_t)i * CC + c) = acc;
        lsum[0] += acc.x; lsum[1] += acc.y; lsum[2] += acc.z; lsum[3] += acc.w;
        lsq[0] += acc.x * acc.x; lsq[1] += acc.y * acc.y; lsq[2] += acc.z * acc.z; lsq[3] += acc.w * acc.w;

        i = __shfl_sync(0xFFFFFFFFu, nexti, 0);
    }

#pragma unroll
    for (int j = 0; j < 4; j++) {
        atomicAdd(&s_stats[c + j], lsum[j]);
        atomicAdd(&s_stats[CC + c + j], lsq[j]);
    }
    __syncthreads();
    if (tid < 64) {
        float4 v = *(float4*)&s_stats[tid * 4];
        float* dstp = g_stats + tid * 4;
        asm volatile("red.global.add.v4.f32 [%0], {%1, %2, %3, %4};"
                     :: "l"(dstp), "f"(v.x), "f"(v.y), "f"(v.z), "f"(v.w)
                     : "memory");
    }
}

// ---------------- out_final = 2*out + batchnorm(aggr) ----------------
__global__ void finalize(const float* __restrict__ gamma, const float* __restrict__ beta,
                         float* __restrict__ out) {
    int i4 = blockIdx.x * blockDim.x + threadIdx.x;
    if (i4 >= NN * 32) return;
    int c = (i4 & 31) * 4;
    float4 a = *(const float4*)(g_aggr + (size_t)i4 * 4);
    float4 o = *(const float4*)(g_out + (size_t)i4 * 4);
    const float inv = 1.0f / NN;
    float4 r;
#pragma unroll
    for (int j = 0; j < 4; j++) {
        float sum = g_stats[c + j];
        float sq = g_stats[CC + c + j];
        float mean = sum * inv;
        float var = sq * inv - mean * mean;
        float scale = rsqrtf(var + 1e-5f) * gamma[c + j];
        float av = (&a.x)[j];
        float ov = (&o.x)[j];
        (&r.x)[j] = 2.0f * ov + (av - mean) * scale + beta[c + j];
    }
    *(float4*)(out + (size_t)i4 * 4) = r;
}

extern "C" void kernel_launch(void* const* d_in, const int* in_sizes, int n_in,
                              void* d_out, int out_size) {
    const float* h    = (const float*)d_in[0];
    const int*   ei   = (const int*)d_in[1];
    const float* ea   = (const float*)d_in[3];
    const float* W0   = (const float*)d_in[4];
    const float* b0   = (const float*)d_in[5];
    const float* Wsh  = (const float*)d_in[6];
    const float* bsh  = (const float*)d_in[7];
    const float* Wf   = (const float*)d_in[8];
    const float* bf   = (const float*)d_in[9];
    const float* Ws   = (const float*)d_in[10];
    const float* bs   = (const float*)d_in[11];
    const float* gamma = (const float*)d_in[12];
    const float* beta  = (const float*)d_in[13];
    float* out = (float*)d_out;

    float *p_stats;
    int *p_deg, *p_total, *p_ticket;
    cudaGetSymbolAddress((void**)&p_stats, g_stats);
    cudaGetSymbolAddress((void**)&p_deg, g_deg);
    cudaGetSymbolAddress((void**)&p_total, g_total);
    cudaGetSymbolAddress((void**)&p_ticket, g_ticket);

    // BOTH branches on non-legacy streams so stream-capture builds a truly
    // parallel DAG (legacy stream 0 would add implicit-sync edges to every node).
    static cudaStream_t s2 = nullptr, s3 = nullptr;
    static cudaEvent_t evFork = nullptr, evJoin2 = nullptr, evJoin3 = nullptr;
    static bool attrSet = false;
    if (!s2) {
        cudaStreamCreateWithFlags(&s2, cudaStreamNonBlocking);
        cudaStreamCreateWithFlags(&s3, cudaStreamNonBlocking);
        cudaEventCreateWithFlags(&evFork, cudaEventDisableTiming);
        cudaEventCreateWithFlags(&evJoin2, cudaEventDisableTiming);
        cudaEventCreateWithFlags(&evJoin3, cudaEventDisableTiming);
    }
    if (!attrSet) {
        cudaFuncSetAttribute(gemm2_tc, cudaFuncAttributeMaxDynamicSharedMemorySize,
                             2 * 128 * LDH * (int)sizeof(__half));
        attrSet = true;
    }

    // ---- fork ----
    cudaEventRecord(evFork, 0);
    cudaStreamWaitEvent(s2, evFork, 0);
    cudaStreamWaitEvent(s3, evFork, 0);

    // branch A (s2): CSR build + edge gaussian (memory-bound)
    cudaMemsetAsync(p_deg, 0, NN * sizeof(int), s2);
    cudaMemsetAsync(p_total, 0, sizeof(int), s2);
    hist<<<(EE + 255) / 256, 256, 0, s2>>>(ei);
    assign_off<<<(NN + 255) / 256, 256, 0, s2>>>();
    edge_gauss_scatter<<<(EE * 8 + 255) / 256, 256, 0, s2>>>(ea, Wsh, bsh, ei);
    cudaEventRecord(evJoin2, s2);

    // branch B (s3): weights + GEMMs (compute-bound)
    cudaMemsetAsync(p_stats, 0, 2 * CC * sizeof(float), s3);
    cudaMemsetAsync(p_ticket, 0, sizeof(int), s3);
    prep_wcat<<<(512 * 128 + 255) / 256, 256, 0, s3>>>(Wf, Ws);
    gemm1<<<(NN + 127) / 128, 256, 0, s3>>>(h, W0, b0, NN);
    gemm2_tc<<<dim3((NN + 127) / 128, 4), 256, 2 * 128 * LDH * sizeof(__half), s3>>>();
    cudaEventRecord(evJoin3, s3);

    // ---- join ----
    cudaStreamWaitEvent(0, evJoin2, 0);
    cudaStreamWaitEvent(0, evJoin3, 0);

    edge_msg_csr<<<1024, 256>>>(Wf, Ws, bf, bs);
    finalize<<<(NN * 32 + 255) / 256, 256>>>(gamma, beta, out);
}

// round 13
// speedup vs baseline: 1.0751x; 1.0108x over previous
#include <cuda_runtime.h>
#include <cuda_fp16.h>
#include <math.h>

#define NN 50000
#define EE 600000
#define CC 128
#define KK 128
#define LDH 136                           // padded smem row, halves

// Scratch (static device globals; no runtime allocation allowed)
__device__ float  g_out[(size_t)NN * CC];      // softplus(h@W0+b0) fp32
__device__ __half g_out16[(size_t)NN * CC];    // fp16 copy (A of TC GEMM)
__device__ float  g_Pi[(size_t)NN * 256];      // fp32 [pi_f | pi_s] per node
// INTERLEAVED fp16 pj: lane l: halves [8l,8l+4) = f ch 4l..4l+3, [8l+4,8l+8) = q.
__device__ __half g_Pj16[(size_t)NN * 256];
__device__ float  g_aggr[(size_t)NN * CC];     // segment-sum result
__device__ float  g_stats[2 * CC];             // per-channel sum, sumsq
__device__ __half g_Wcat16T[512 * 128];        // packed weights, TRANSPOSED [n][k], fp16
// CSR scratch
__device__ int    g_deg[NN];
__device__ int    g_roff[NN];
__device__ int    g_cursor[NN];
__device__ int    g_total;
__device__ int    g_ticket;                    // work-steal counter for edge_msg
__device__ int2   g_epack[EE];                 // (src, e-bits) grouped by dst row

__device__ __forceinline__ float sp_f(float x) {
    return x > 15.0f ? x : __logf(1.0f + __expf(x));
}
__device__ __forceinline__ float sigm_f(float x) {
    float t;
    asm("tanh.approx.f32 %0, %1;" : "=f"(t) : "f"(x * 0.5f));
    return fmaf(0.5f, t, 0.5f);
}

// ---------------- GEMM1 (fp32 SIMT): out = softplus(h@W0 + b0), + fp16 copy ----
// Last block instead performs weight packing (prep_wcat) + zeroes stats/ticket.
__global__ void __launch_bounds__(256, 2)
gemm1(const float* __restrict__ A, const float* __restrict__ B,
      const float* __restrict__ bias, int M,
      const float* __restrict__ Wf, const float* __restrict__ Ws) {
    if (blockIdx.x == gridDim.x - 1) {
        // weight packing block: Wcat16T[n][k], n-major
        int tid = threadIdx.x;
        for (int idx = tid; idx < 512 * 128; idx += 256) {
            int n = idx >> 7;
            int k = idx & 127;
            float v;
            if (n < 128)      v = Wf[k * 128 + n];
            else if (n < 256) v = Ws[k * 128 + (n - 128)];
            else if (n < 384) v = Wf[(128 + k) * 128 + (n - 256)];
            else              v = Ws[(128 + k) * 128 + (n - 384)];
            g_Wcat16T[idx] = __float2half(v);
        }
        if (tid < 2 * CC) g_stats[tid] = 0.0f;
        if (tid == 0) g_ticket = 0;
        return;
    }

    __shared__ float As[16][132];
    __shared__ float Bs[16][128];
    int tid = threadIdx.x;
    int tx = tid & 15, ty = tid >> 4;
    int row0 = blockIdx.x * 128;
    float acc[8][8] = {};

    for (int kc = 0; kc < KK; kc += 16) {
#pragma unroll
        for (int l = 0; l < 2; l++) {
            int f = tid + l * 256;
            int m = f >> 2;
            int kq = (f & 3) << 2;
            int gr = row0 + m;
            float4 av = make_float4(0.f, 0.f, 0.f, 0.f);
            if (gr < M) av = *(const float4*)(A + (size_t)gr * KK + kc + kq);
            As[kq + 0][m] = av.x;
            As[kq + 1][m] = av.y;
            As[kq + 2][m] = av.z;
            As[kq + 3][m] = av.w;
        }
#pragma unroll
        for (int l = 0; l < 2; l++) {
            int f = tid + l * 256;
            int k = f >> 5;
            int c4 = (f & 31) << 2;
            *(float4*)&Bs[k][c4] = *(const float4*)(B + (size_t)(kc + k) * CC + c4);
        }
        __syncthreads();
#pragma unroll
        for (int k = 0; k < 16; k++) {
            float4 a0 = *(float4*)&As[k][ty * 4];
            float4 a1 = *(float4*)&As[k][64 + ty * 4];
            float4 b0 = *(float4*)&Bs[k][tx * 4];
            float4 b1 = *(float4*)&Bs[k][64 + tx * 4];
            float ar[8] = {a0.x, a0.y, a0.z, a0.w, a1.x, a1.y, a1.z, a1.w};
            float br[8] = {b0.x, b0.y, b0.z, b0.w, b1.x, b1.y, b1.z, b1.w};
#pragma unroll
            for (int i = 0; i < 8; i++)
#pragma unroll
                for (int j = 0; j < 8; j++)
                    acc[i][j] += ar[i] * br[j];
        }
        __syncthreads();
    }

#pragma unroll
    for (int i = 0; i < 8; i++) {
        int gr = row0 + (i < 4 ? ty * 4 + i : 64 + ty * 4 + (i - 4));
        if (gr >= M) continue;
#pragma unroll
        for (int half = 0; half < 2; half++) {
            int gc = half * 64 + tx * 4;
            float4 v;
            v.x = sp_f(acc[i][half * 4 + 0] + bias[gc + 0]);
            v.y = sp_f(acc[i][half * 4 + 1] + bias[gc + 1]);
            v.z = sp_f(acc[i][half * 4 + 2] + bias[gc + 2]);
            v.w = sp_f(acc[i][half * 4 + 3] + bias[gc + 3]);
            *(float4*)(g_out + (size_t)gr * CC + gc) = v;
            __half2 h0 = __floats2half2_rn(v.x, v.y);
            __half2 h1 = __floats2half2_rn(v.z, v.w);
            uint2 u;
            u.x = *(unsigned*)&h0;
            u.y = *(unsigned*)&h1;
            *(uint2*)(g_out16 + (size_t)gr * CC + gc) = u;
        }
    }
}

// ---------------- GEMM2 (fp16 tensor core): P = out @ Wcat ----------------
__global__ void __launch_bounds__(256, 2)
gemm2_tc() {
    extern __shared__ __half smemh[];
    __half* As = smemh;                 // [128][LDH]
    __half* Bs = smemh + 128 * LDH;     // [128][LDH], row n, col k
    int tid = threadIdx.x;
    int row0 = blockIdx.x * 128;
    int nblk = blockIdx.y;

#pragma unroll
    for (int l = 0; l < 8; l++) {
        int idx = tid + l * 256;
        int r = idx >> 4;
        int c8 = (idx & 15) << 3;
        int4 v = make_int4(0, 0, 0, 0);
        int gr = row0 + r;
        if (gr < NN) v = *(const int4*)(g_out16 + (size_t)gr * CC + c8);
        *(int4*)(As + r * LDH + c8) = v;
        int4 w = *(const int4*)(g_Wcat16T + ((size_t)(nblk * 128 + r)) * CC + c8);
        *(int4*)(Bs + r * LDH + c8) = w;
    }
    __syncthreads();

    int lane = tid & 31;
    int w = tid >> 5;
    int g = lane >> 2, tig = lane & 3;
    int wm = (w & 1) * 64, wn = (w >> 1) * 32;

    float acc[4][4][4];
#pragma unroll
    for (int mt = 0; mt < 4; mt++)
#pragma unroll
        for (int nt = 0; nt < 4; nt++)
#pragma unroll
            for (int q = 0; q < 4; q++) acc[mt][nt][q] = 0.f;

    const unsigned* As2 = (const unsigned*)As;
    const unsigned* Bs2 = (const unsigned*)Bs;

#pragma unroll
    for (int ks = 0; ks < 8; ks++) {
        int kk = ks * 8;
        unsigned a[4][4], b[4][2];
#pragma unroll
        for (int mt = 0; mt < 4; mt++) {
            int r = wm + mt * 16 + g;
            a[mt][0] = As2[r * 68 + kk + tig];
            a[mt][1] = As2[(r + 8) * 68 + kk + tig];
            a[mt][2] = As2[r * 68 + kk + 4 + tig];
            a[mt][3] = As2[(r + 8) * 68 + kk + 4 + tig];
        }
#pragma unroll
        for (int nt = 0; nt < 4; nt++) {
            int r = wn + nt * 8 + g;
            b[nt][0] = Bs2[r * 68 + kk + tig];
            b[nt][1] = Bs2[r * 68 + kk + 4 + tig];
        }
#pragma unroll
        for (int mt = 0; mt < 4; mt++)
#pragma unroll
            for (int nt = 0; nt < 4; nt++) {
                asm volatile(
                    "mma.sync.aligned.m16n8k16.row.col.f32.f16.f16.f32 "
                    "{%0,%1,%2,%3}, {%4,%5,%6,%7}, {%8,%9}, {%0,%1,%2,%3};"
                    : "+f"(acc[mt][nt][0]), "+f"(acc[mt][nt][1]),
                      "+f"(acc[mt][nt][2]), "+f"(acc[mt][nt][3])
                    : "r"(a[mt][0]), "r"(a[mt][1]), "r"(a[mt][2]), "r"(a[mt][3]),
                      "r"(b[nt][0]), "r"(b[nt][1]));
            }
    }

#pragma unroll
    for (int mt = 0; mt < 4; mt++) {
#pragma unroll
        for (int nt = 0; nt < 4; nt++) {
            int gr0 = row0 + wm + mt * 16 + g;
            int gr1 = gr0 + 8;
            float d0 = acc[mt][nt][0], d1 = acc[mt][nt][1];
            float d2 = acc[mt][nt][2], d3 = acc[mt][nt][3];
            if (nblk < 2) {
                int col = nblk * 128 + wn + nt * 8 + tig * 2;
                if (gr0 < NN) *(float2*)(g_Pi + (size_t)gr0 * 256 + col) = make_float2(d0, d1);
                if (gr1 < NN) *(float2*)(g_Pi + (size_t)gr1 * 256 + col) = make_float2(d2, d3);
            } else {
                int c0 = wn + nt * 8 + tig * 2;                 // channel 0..127 (even)
                int hoff = ((c0 >> 2) << 3) + (c0 & 3) + (nblk == 3 ? 4 : 0);
                __half2 h01 = __floats2half2_rn(d0, d1);
                __half2 h23 = __floats2half2_rn(d2, d3);
                if (gr0 < NN) *(unsigned*)(g_Pj16 + (size_t)gr0 * 256 + hoff) = *(unsigned*)&h01;
                if (gr1 < NN) *(unsigned*)(g_Pj16 + (size_t)gr1 * 256 + hoff) = *(unsigned*)&h23;
            }
        }
    }
}

// ---------------- CSR build ----------------
__global__ void hist(const int* __restrict__ ei) {
    int e = blockIdx.x * blockDim.x + threadIdx.x;
    if (e == 0) g_total = 0;                      // zero scan base for assign_off
    if (e < EE) atomicAdd(&g_deg[ei[EE + e]], 1);
}

__global__ void assign_off() {
    int i = blockIdx.x * blockDim.x + threadIdx.x;
    if (i < NN) {
        int d = g_deg[i];
        int r = atomicAdd(&g_total, d);
        g_roff[i] = r;
        g_cursor[i] = r;
    }
}

// ---------------- e = softplus(edge_attr @ Wsh + bsh) fused with CSR scatter
__global__ void edge_gauss_scatter(const float* __restrict__ ea,
                                   const float* __restrict__ Wsh,
                                   const float* __restrict__ bsh,
                                   const int* __restrict__ ei) {
    int t = blockIdx.x * blockDim.x + threadIdx.x;
    int e = t >> 3;
    if (e >= EE) return;
    int l = t & 7;
    const float4* base = (const float4*)(ea + (size_t)e * 128) + l * 4;
    const float4* wb = (const float4*)Wsh + l * 4;
    float4 a0 = base[0], a1 = base[1], a2 = base[2], a3 = base[3];
    float4 w0 = wb[0], w1 = wb[1], w2 = wb[2], w3 = wb[3];
    float d = a0.x * w0.x + a0.y * w0.y + a0.z * w0.z + a0.w * w0.w
            + a1.x * w1.x + a1.y * w1.y + a1.z * w1.z + a1.w * w1.w
            + a2.x * w2.x + a2.y * w2.y + a2.z * w2.z + a2.w * w2.w
            + a3.x * w3.x + a3.y * w3.y + a3.z * w3.z + a3.w * w3.w;
#pragma unroll
    for (int o = 4; o; o >>= 1) d += __shfl_xor_sync(0xFFFFFFFFu, d, o);
    if (l == 0) {
        float ev = sp_f(d + bsh[0]);
        int src = __ldg(ei + e);
        int dst = __ldg(ei + EE + e);
        int pos = atomicAdd(&g_cursor[dst], 1);
        g_epack[pos] = make_int2(src, __float_as_int(ev));
    }
}

// ---------------- CSR edge messages + fused BN stats (work-stealing) ------
__device__ __forceinline__ void pj_load(int src, int lane, float4& f, float4& q) {
    uint4 v = *(const uint4*)(g_Pj16 + (size_t)src * 256 + lane * 8);
    float2 f01 = __half22float2(*(__half2*)&v.x);
    float2 f23 = __half22float2(*(__half2*)&v.y);
    float2 q01 = __half22float2(*(__half2*)&v.z);
    float2 q23 = __half22float2(*(__half2*)&v.w);
    f = make_float4(f01.x, f01.y, f23.x, f23.y);
    q = make_float4(q01.x, q01.y, q23.x, q23.y);
}

__device__ __forceinline__ void msg_add(float4& acc, const float4& pif, const float4& pis,
                                        const float4& f, const float4& q, float ev,
                                        const float4& wfe, const float4& wse) {
    acc.x += sigm_f(pif.x + f.x + ev * wfe.x) * sp_f(pis.x + q.x + ev * wse.x);
    acc.y += sigm_f(pif.y + f.y + ev * wfe.y) * sp_f(pis.y + q.y + ev * wse.y);
    acc.z += sigm_f(pif.z + f.z + ev * wfe.z) * sp_f(pis.z + q.z + ev * wse.z);
    acc.w += sigm_f(pif.w + f.w + ev * wfe.w) * sp_f(pis.w + q.w + ev * wse.w);
}

__global__ void __launch_bounds__(256)
edge_msg_csr(const float* __restrict__ Wf, const float* __restrict__ Ws,
             const float* __restrict__ bf, const float* __restrict__ bs) {
    __shared__ float s_stats[2 * CC];
    int tid = threadIdx.x;
    int lane = tid & 31;
    int c = lane * 4;
    s_stats[tid] = 0.0f;
    __syncthreads();

    float4 wfe = *(const float4*)(Wf + 256 * 128 + c);
    float4 wse = *(const float4*)(Ws + 256 * 128 + c);
    float4 bfv = *(const float4*)(bf + c);
    float4 bsv = *(const float4*)(bs + c);

    float lsum[4] = {}, lsq[4] = {};

    int i = 0;
    if (lane == 0) i = atomicAdd(&g_ticket, 1);
    i = __shfl_sync(0xFFFFFFFFu, i, 0);

    while (i < NN) {
        int nexti = 0;
        if (lane == 0) nexti = atomicAdd(&g_ticket, 1);   // prefetch next ticket

        const float4* Pi = (const float4*)(g_Pi + (size_t)i * 256);
        float4 pif = Pi[lane];
        float4 pis = Pi[32 + lane];
        pif.x += bfv.x; pif.y += bfv.y; pif.z += bfv.z; pif.w += bfv.w;
        pis.x += bsv.x; pis.y += bsv.y; pis.z += bsv.z; pis.w += bsv.w;
        int k = g_roff[i];
        int end = g_cursor[i];
        float4 acc = make_float4(0.f, 0.f, 0.f, 0.f);

        for (; k + 4 <= end; k += 4) {
            int2 p0 = g_epack[k], p1 = g_epack[k + 1];
            int2 p2 = g_epack[k + 2], p3 = g_epack[k + 3];
            float4 f0, q0, f1, q1, f2, q2, f3, q3;
            pj_load(p0.x, lane, f0, q0);
            pj_load(p1.x, lane, f1, q1);
            pj_load(p2.x, lane, f2, q2);
            pj_load(p3.x, lane, f3, q3);
            msg_add(acc, pif, pis, f0, q0, __int_as_float(p0.y), wfe, wse);
            msg_add(acc, pif, pis, f1, q1, __int_as_float(p1.y), wfe, wse);
            msg_add(acc, pif, pis, f2, q2, __int_as_float(p2.y), wfe, wse);
            msg_add(acc, pif, pis, f3, q3, __int_as_float(p3.y), wfe, wse);
        }
        for (; k < end; k++) {
            int2 p0 = g_epack[k];
            float4 f0, q0;
            pj_load(p0.x, lane, f0, q0);
            msg_add(acc, pif, pis, f0, q0, __int_as_float(p0.y), wfe, wse);
        }
        *(float4*)(g_aggr + (size_t)i * CC + c) = acc;
        lsum[0] += acc.x; lsum[1] += acc.y; lsum[2] += acc.z; lsum[3] += acc.w;
        lsq[0] += acc.x * acc.x; lsq[1] += acc.y * acc.y; lsq[2] += acc.z * acc.z; lsq[3] += acc.w * acc.w;

        i = __shfl_sync(0xFFFFFFFFu, nexti, 0);
    }

#pragma unroll
    for (int j = 0; j < 4; j++) {
        atomicAdd(&s_stats[c + j], lsum[j]);
        atomicAdd(&s_stats[CC + c + j], lsq[j]);
    }
    __syncthreads();
    if (tid < 64) {
        float4 v = *(float4*)&s_stats[tid * 4];
        float* dstp = g_stats + tid * 4;
        asm volatile("red.global.add.v4.f32 [%0], {%1, %2, %3, %4};"
                     :: "l"(dstp), "f"(v.x), "f"(v.y), "f"(v.z), "f"(v.w)
                     : "memory");
    }
}

// ---------------- out_final = 2*out + batchnorm(aggr) ----------------
__global__ void finalize(const float* __restrict__ gamma, const float* __restrict__ beta,
                         float* __restrict__ out) {
    int i4 = blockIdx.x * blockDim.x + threadIdx.x;
    if (i4 >= NN * 32) return;
    int c = (i4 & 31) * 4;
    float4 a = *(const float4*)(g_aggr + (size_t)i4 * 4);
    float4 o = *(const float4*)(g_out + (size_t)i4 * 4);
    const float inv = 1.0f / NN;
    float4 r;
#pragma unroll
    for (int j = 0; j < 4; j++) {
        float sum = g_stats[c + j];
        float sq = g_stats[CC + c + j];
        float mean = sum * inv;
        float var = sq * inv - mean * mean;
        float scale = rsqrtf(var + 1e-5f) * gamma[c + j];
        float av = (&a.x)[j];
        float ov = (&o.x)[j];
        (&r.x)[j] = 2.0f * ov + (av - mean) * scale + beta[c + j];
    }
    *(float4*)(out + (size_t)i4 * 4) = r;
}

extern "C" void kernel_launch(void* const* d_in, const int* in_sizes, int n_in,
                              void* d_out, int out_size) {
    const float* h    = (const float*)d_in[0];
    const int*   ei   = (const int*)d_in[1];
    const float* ea   = (const float*)d_in[3];
    const float* W0   = (const float*)d_in[4];
    const float* b0   = (const float*)d_in[5];
    const float* Wsh  = (const float*)d_in[6];
    const float* bsh  = (const float*)d_in[7];
    const float* Wf   = (const float*)d_in[8];
    const float* bf   = (const float*)d_in[9];
    const float* Ws   = (const float*)d_in[10];
    const float* bs   = (const float*)d_in[11];
    const float* gamma = (const float*)d_in[12];
    const float* beta  = (const float*)d_in[13];
    float* out = (float*)d_out;

    int *p_deg;
    cudaGetSymbolAddress((void**)&p_deg, g_deg);

    // BOTH branches on non-legacy streams for a truly parallel captured DAG.
    static cudaStream_t s2 = nullptr, s3 = nullptr;
    static cudaEvent_t evFork = nullptr, evJoin2 = nullptr, evJoin3 = nullptr;
    static bool attrSet = false;
    if (!s2) {
        cudaStreamCreateWithFlags(&s2, cudaStreamNonBlocking);
        cudaStreamCreateWithFlags(&s3, cudaStreamNonBlocking);
        cudaEventCreateWithFlags(&evFork, cudaEventDisableTiming);
        cudaEventCreateWithFlags(&evJoin2, cudaEventDisableTiming);
        cudaEventCreateWithFlags(&evJoin3, cudaEventDisableTiming);
    }
    if (!attrSet) {
        cudaFuncSetAttribute(gemm2_tc, cudaFuncAttributeMaxDynamicSharedMemorySize,
                             2 * 128 * LDH * (int)sizeof(__half));
        attrSet = true;
    }

    // ---- fork ----
    cudaEventRecord(evFork, 0);
    cudaStreamWaitEvent(s2, evFork, 0);
    cudaStreamWaitEvent(s3, evFork, 0);

    // branch A (s2): CSR build + edge gaussian (memory-bound)
    cudaMemsetAsync(p_deg, 0, NN * sizeof(int), s2);
    hist<<<(EE + 255) / 256, 256, 0, s2>>>(ei);
    assign_off<<<(NN + 255) / 256, 256, 0, s2>>>();
    edge_gauss_scatter<<<(EE * 8 + 255) / 256, 256, 0, s2>>>(ea, Wsh, bsh, ei);
    cudaEventRecord(evJoin2, s2);

    // branch B (s3): GEMMs; gemm1's extra block packs weights + zeroes stats/ticket
    gemm1<<<(NN + 127) / 128 + 1, 256, 0, s3>>>(h, W0, b0, NN, Wf, Ws);
    gemm2_tc<<<dim3((NN + 127) / 128, 4), 256, 2 * 128 * LDH * sizeof(__half), s3>>>();
    cudaEventRecord(evJoin3, s3);

    // ---- join ----
    cudaStreamWaitEvent(0, evJoin2, 0);
    cudaStreamWaitEvent(0, evJoin3, 0);

    edge_msg_csr<<<1024, 256>>>(Wf, Ws, bf, bs);
    finalize<<<(NN * 32 + 255) / 256, 256>>>(gamma, beta, out);
}

// round 14
// speedup vs baseline: 1.2110x; 1.1264x over previous
#include <cuda_runtime.h>
#include <cuda_fp16.h>
#include <math.h>

#define NN 50000
#define EE 600000
#define CC 128
#define KK 128
#define LDH 136                           // padded smem row, halves (68 half2)

// Scratch (static device globals; no runtime allocation allowed)
__device__ float  g_out[(size_t)NN * CC];      // softplus(h@W0+b0) fp32
__device__ float  g_Pi[(size_t)NN * 256];      // fp32 [pi_f | pi_s] per node
// INTERLEAVED fp16 pj: lane l: halves [8l,8l+4) = f ch 4l..4l+3, [8l+4,8l+8) = q.
__device__ __half g_Pj16[(size_t)NN * 256];
__device__ float  g_aggr[(size_t)NN * CC];     // segment-sum result
__device__ float  g_stats[2 * CC];             // per-channel sum, sumsq
__device__ __half g_W016T[128 * 128];          // W0 transposed [n][k], fp16
__device__ __half g_Wcat16T[512 * 128];        // packed weights, TRANSPOSED [n][k], fp16
// CSR scratch
__device__ int    g_deg[NN];
__device__ int    g_roff[NN];
__device__ int    g_cursor[NN];
__device__ int    g_total;
__device__ int    g_ticket;                    // work-steal counter for edge_msg
__device__ int2   g_epack[EE];                 // (src, e-bits) grouped by dst row

__device__ __forceinline__ float sp_f(float x) {
    return x > 15.0f ? x : __logf(1.0f + __expf(x));
}
__device__ __forceinline__ float sigm_f(float x) {
    float t;
    asm("tanh.approx.f32 %0, %1;" : "=f"(t) : "f"(x * 0.5f));
    return fmaf(0.5f, t, 0.5f);
}

// ---------------- weight packing: W0T + WcatT (fp16, [n][k]) + zero stats ----
__global__ void prep_pack(const float* __restrict__ W0,
                          const float* __restrict__ Wf, const float* __restrict__ Ws) {
    int idx = blockIdx.x * blockDim.x + threadIdx.x;   // n_all*128 + k, n_all 0..639
    if (idx < 640 * 128) {
        int n_all = idx >> 7;
        int k = idx & 127;
        float v;
        if (n_all < 128) {
            v = W0[k * 128 + n_all];
            g_W016T[idx] = __float2half(v);
        } else {
            int n = n_all - 128;
            if (n < 128)      v = Wf[k * 128 + n];
            else if (n < 256) v = Ws[k * 128 + (n - 128)];
            else if (n < 384) v = Wf[(128 + k) * 128 + (n - 256)];
            else              v = Ws[(128 + k) * 128 + (n - 384)];
            g_Wcat16T[(size_t)n * 128 + k] = __float2half(v);
        }
    }
    if (blockIdx.x == 0) {
        if (threadIdx.x < 2 * CC) g_stats[threadIdx.x] = 0.0f;
        if (threadIdx.x == 0) g_ticket = 0;
    }
}

// ---------------- Fused node GEMMs (fp16 tensor core) ----------------------
// Stage 1: out_tile = softplus(h_tile @ W0 + b0)  -> g_out (fp32) + smem fp16
// Stage 2: P_tile = out_tile @ Wcat (4 x 128-col blocks) -> g_Pi / g_Pj16
// 8 warps (2M x 4N), warp tile 64x32, m16n8k16, full K=128 in smem.
__global__ void __launch_bounds__(256, 2)
node_gemms(const float* __restrict__ h, const float* __restrict__ bias) {
    extern __shared__ __half smemh[];
    __half* As = smemh;                 // [128][LDH]  (h16, then out16)
    __half* Bs = smemh + 128 * LDH;     // [128][LDH]  (weight tiles [n][k])
    int tid = threadIdx.x;
    int row0 = blockIdx.x * 128;

    // Load h tile fp32 -> fp16 smem
#pragma unroll
    for (int l = 0; l < 16; l++) {
        int f = tid + l * 256;          // float4 id 0..4095
        int r = f >> 5;                 // row 0..127
        int c4 = (f & 31) << 2;         // col 0,4,..,124
        int gr = row0 + r;
        float4 v = make_float4(0.f, 0.f, 0.f, 0.f);
        if (gr < NN) v = *(const float4*)(h + (size_t)gr * KK + c4);
        __half2 h0 = __floats2half2_rn(v.x, v.y);
        __half2 h1 = __floats2half2_rn(v.z, v.w);
        uint2 u;
        u.x = *(unsigned*)&h0;
        u.y = *(unsigned*)&h1;
        *(uint2*)(As + r * LDH + c4) = u;
    }
    // Load W0T tile
#pragma unroll
    for (int l = 0; l < 8; l++) {
        int idx = tid + l * 256;
        int r = idx >> 4;
        int c8 = (idx & 15) << 3;
        *(int4*)(Bs + r * LDH + c8) = *(const int4*)(g_W016T + (size_t)r * CC + c8);
    }
    __syncthreads();

    int lane = tid & 31;
    int w = tid >> 5;
    int g = lane >> 2, tig = lane & 3;
    int wm = (w & 1) * 64, wn = (w >> 1) * 32;

    const unsigned* As2 = (const unsigned*)As;
    const unsigned* Bs2 = (const unsigned*)Bs;

    float acc[4][4][4];

    // ---- Stage 1: h @ W0 ----
#pragma unroll
    for (int mt = 0; mt < 4; mt++)
#pragma unroll
        for (int nt = 0; nt < 4; nt++)
#pragma unroll
            for (int q = 0; q < 4; q++) acc[mt][nt][q] = 0.f;

#pragma unroll
    for (int ks = 0; ks < 8; ks++) {
        int kk = ks * 8;
        unsigned a[4][4], b[4][2];
#pragma unroll
        for (int mt = 0; mt < 4; mt++) {
            int r = wm + mt * 16 + g;
            a[mt][0] = As2[r * 68 + kk + tig];
            a[mt][1] = As2[(r + 8) * 68 + kk + tig];
            a[mt][2] = As2[r * 68 + kk + 4 + tig];
            a[mt][3] = As2[(r + 8) * 68 + kk + 4 + tig];
        }
#pragma unroll
        for (int nt = 0; nt < 4; nt++) {
            int r = wn + nt * 8 + g;
            b[nt][0] = Bs2[r * 68 + kk + tig];
            b[nt][1] = Bs2[r * 68 + kk + 4 + tig];
        }
#pragma unroll
        for (int mt = 0; mt < 4; mt++)
#pragma unroll
            for (int nt = 0; nt < 4; nt++) {
                asm volatile(
                    "mma.sync.aligned.m16n8k16.row.col.f32.f16.f16.f32 "
                    "{%0,%1,%2,%3}, {%4,%5,%6,%7}, {%8,%9}, {%0,%1,%2,%3};"
                    : "+f"(acc[mt][nt][0]), "+f"(acc[mt][nt][1]),
                      "+f"(acc[mt][nt][2]), "+f"(acc[mt][nt][3])
                    : "r"(a[mt][0]), "r"(a[mt][1]), "r"(a[mt][2]), "r"(a[mt][3]),
                      "r"(b[nt][0]), "r"(b[nt][1]));
            }
    }
    __syncthreads();   // all warps done reading As (h16) before overwrite

    // Stage-1 epilogue: softplus + bias -> g_out fp32, out16 -> As (reuse)
#pragma unroll
    for (int mt = 0; mt < 4; mt++) {
#pragma unroll
        for (int nt = 0; nt < 4; nt++) {
            int r0 = wm + mt * 16 + g;
            int r1 = r0 + 8;
            int col = wn + nt * 8 + tig * 2;
            float bb0 = bias[col], bb1 = bias[col + 1];
            float o0 = sp_f(acc[mt][nt][0] + bb0);
            float o1 = sp_f(acc[mt][nt][1] + bb1);
            float o2 = sp_f(acc[mt][nt][2] + bb0);
            float o3 = sp_f(acc[mt][nt][3] + bb1);
            __half2 h01 = __floats2half2_rn(o0, o1);
            __half2 h23 = __floats2half2_rn(o2, o3);
            *(unsigned*)(As + r0 * LDH + col) = *(unsigned*)&h01;
            *(unsigned*)(As + r1 * LDH + col) = *(unsigned*)&h23;
            int gr0 = row0 + r0, gr1 = row0 + r1;
            if (gr0 < NN) *(float2*)(g_out + (size_t)gr0 * CC + col) = make_float2(o0, o1);
            if (gr1 < NN) *(float2*)(g_out + (size_t)gr1 * CC + col) = make_float2(o2, o3);
        }
    }
    __syncthreads();   // out16 complete in As

    // ---- Stage 2: out @ Wcat, 4 n-blocks ----
    for (int nblk = 0; nblk < 4; nblk++) {
        // load Wcat block [nblk*128 .. +128)[k] into Bs
#pragma unroll
        for (int l = 0; l < 8; l++) {
            int idx = tid + l * 256;
            int r = idx >> 4;
            int c8 = (idx & 15) << 3;
            *(int4*)(Bs + r * LDH + c8) =
                *(const int4*)(g_Wcat16T + ((size_t)(nblk * 128 + r)) * CC + c8);
        }
        __syncthreads();

#pragma unroll
        for (int mt = 0; mt < 4; mt++)
#pragma unroll
            for (int nt = 0; nt < 4; nt++)
#pragma unroll
                for (int q = 0; q < 4; q++) acc[mt][nt][q] = 0.f;

#pragma unroll
        for (int ks = 0; ks < 8; ks++) {
            int kk = ks * 8;
            unsigned a[4][4], b[4][2];
#pragma unroll
            for (int mt = 0; mt < 4; mt++) {
                int r = wm + mt * 16 + g;
                a[mt][0] = As2[r * 68 + kk + tig];
                a[mt][1] = As2[(r + 8) * 68 + kk + tig];
                a[mt][2] = As2[r * 68 + kk + 4 + tig];
                a[mt][3] = As2[(r + 8) * 68 + kk + 4 + tig];
            }
#pragma unroll
            for (int nt = 0; nt < 4; nt++) {
                int r = wn + nt * 8 + g;
                b[nt][0] = Bs2[r * 68 + kk + tig];
                b[nt][1] = Bs2[r * 68 + kk + 4 + tig];
            }
#pragma unroll
            for (int mt = 0; mt < 4; mt++)
#pragma unroll
                for (int nt = 0; nt < 4; nt++) {
                    asm volatile(
                        "mma.sync.aligned.m16n8k16.row.col.f32.f16.f16.f32 "
                        "{%0,%1,%2,%3}, {%4,%5,%6,%7}, {%8,%9}, {%0,%1,%2,%3};"
                        : "+f"(acc[mt][nt][0]), "+f"(acc[mt][nt][1]),
                          "+f"(acc[mt][nt][2]), "+f"(acc[mt][nt][3])
                        : "r"(a[mt][0]), "r"(a[mt][1]), "r"(a[mt][2]), "r"(a[mt][3]),
                          "r"(b[nt][0]), "r"(b[nt][1]));
                }
        }

        // Stage-2 epilogue: nblk 0,1 -> Pi fp32; nblk 2 -> Pj f; nblk 3 -> Pj q
#pragma unroll
        for (int mt = 0; mt < 4; mt++) {
#pragma unroll
            for (int nt = 0; nt < 4; nt++) {
                int gr0 = row0 + wm + mt * 16 + g;
                int gr1 = gr0 + 8;
                float d0 = acc[mt][nt][0], d1 = acc[mt][nt][1];
                float d2 = acc[mt][nt][2], d3 = acc[mt][nt][3];
                if (nblk < 2) {
                    int col = nblk * 128 + wn + nt * 8 + tig * 2;
                    if (gr0 < NN) *(float2*)(g_Pi + (size_t)gr0 * 256 + col) = make_float2(d0, d1);
                    if (gr1 < NN) *(float2*)(g_Pi + (size_t)gr1 * 256 + col) = make_float2(d2, d3);
                } else {
                    int c0 = wn + nt * 8 + tig * 2;
                    int hoff = ((c0 >> 2) << 3) + (c0 & 3) + (nblk == 3 ? 4 : 0);
                    __half2 h01 = __floats2half2_rn(d0, d1);
                    __half2 h23 = __floats2half2_rn(d2, d3);
                    if (gr0 < NN) *(unsigned*)(g_Pj16 + (size_t)gr0 * 256 + hoff) = *(unsigned*)&h01;
                    if (gr1 < NN) *(unsigned*)(g_Pj16 + (size_t)gr1 * 256 + hoff) = *(unsigned*)&h23;
                }
            }
        }
        __syncthreads();   // before next Bs overwrite
    }
}

// ---------------- CSR build ----------------
__global__ void hist(const int* __restrict__ ei) {
    int e = blockIdx.x * blockDim.x + threadIdx.x;
    if (e == 0) g_total = 0;
    if (e < EE) atomicAdd(&g_deg[ei[EE + e]], 1);
}

__global__ void assign_off() {
    int i = blockIdx.x * blockDim.x + threadIdx.x;
    if (i < NN) {
        int d = g_deg[i];
        int r = atomicAdd(&g_total, d);
        g_roff[i] = r;
        g_cursor[i] = r;
    }
}

// ---------------- e = softplus(edge_attr @ Wsh + bsh) fused with CSR scatter
__global__ void edge_gauss_scatter(const float* __restrict__ ea,
                                   const float* __restrict__ Wsh,
                                   const float* __restrict__ bsh,
                                   const int* __restrict__ ei) {
    int t = blockIdx.x * blockDim.x + threadIdx.x;
    int e = t >> 3;
    if (e >= EE) return;
    int l = t & 7;
    const float4* base = (const float4*)(ea + (size_t)e * 128) + l * 4;
    const float4* wb = (const float4*)Wsh + l * 4;
    float4 a0 = base[0], a1 = base[1], a2 = base[2], a3 = base[3];
    float4 w0 = wb[0], w1 = wb[1], w2 = wb[2], w3 = wb[3];
    float d = a0.x * w0.x + a0.y * w0.y + a0.z * w0.z + a0.w * w0.w
            + a1.x * w1.x + a1.y * w1.y + a1.z * w1.z + a1.w * w1.w
            + a2.x * w2.x + a2.y * w2.y + a2.z * w2.z + a2.w * w2.w
            + a3.x * w3.x + a3.y * w3.y + a3.z * w3.z + a3.w * w3.w;
#pragma unroll
    for (int o = 4; o; o >>= 1) d += __shfl_xor_sync(0xFFFFFFFFu, d, o);
    if (l == 0) {
        float ev = sp_f(d + bsh[0]);
        int src = __ldg(ei + e);
        int dst = __ldg(ei + EE + e);
        int pos = atomicAdd(&g_cursor[dst], 1);
        g_epack[pos] = make_int2(src, __float_as_int(ev));
    }
}

// ---------------- CSR edge messages + fused BN stats (work-stealing) ------
__device__ __forceinline__ void pj_load(int src, int lane, float4& f, float4& q) {
    uint4 v = *(const uint4*)(g_Pj16 + (size_t)src * 256 + lane * 8);
    float2 f01 = __half22float2(*(__half2*)&v.x);
    float2 f23 = __half22float2(*(__half2*)&v.y);
    float2 q01 = __half22float2(*(__half2*)&v.z);
    float2 q23 = __half22float2(*(__half2*)&v.w);
    f = make_float4(f01.x, f01.y, f23.x, f23.y);
    q = make_float4(q01.x, q01.y, q23.x, q23.y);
}

__device__ __forceinline__ void msg_add(float4& acc, const float4& pif, const float4& pis,
                                        const float4& f, const float4& q, float ev,
                                        const float4& wfe, const float4& wse) {
    acc.x += sigm_f(pif.x + f.x + ev * wfe.x) * sp_f(pis.x + q.x + ev * wse.x);
    acc.y += sigm_f(pif.y + f.y + ev * wfe.y) * sp_f(pis.y + q.y + ev * wse.y);
    acc.z += sigm_f(pif.z + f.z + ev * wfe.z) * sp_f(pis.z + q.z + ev * wse.z);
    acc.w += sigm_f(pif.w + f.w + ev * wfe.w) * sp_f(pis.w + q.w + ev * wse.w);
}

__global__ void __launch_bounds__(256)
edge_msg_csr(const float* __restrict__ Wf, const float* __restrict__ Ws,
             const float* __restrict__ bf, const float* __restrict__ bs) {
    __shared__ float s_stats[2 * CC];
    int tid = threadIdx.x;
    int lane = tid & 31;
    int c = lane * 4;
    s_stats[tid] = 0.0f;
    __syncthreads();

    float4 wfe = *(const float4*)(Wf + 256 * 128 + c);
    float4 wse = *(const float4*)(Ws + 256 * 128 + c);
    float4 bfv = *(const float4*)(bf + c);
    float4 bsv = *(const float4*)(bs + c);

    float lsum[4] = {}, lsq[4] = {};

    int i = 0;
    if (lane == 0) i = atomicAdd(&g_ticket, 1);
    i = __shfl_sync(0xFFFFFFFFu, i, 0);

    while (i < NN) {
        int nexti = 0;
        if (lane == 0) nexti = atomicAdd(&g_ticket, 1);   // prefetch next ticket

        const float4* Pi = (const float4*)(g_Pi + (size_t)i * 256);
        float4 pif = Pi[lane];
        float4 pis = Pi[32 + lane];
        pif.x += bfv.x; pif.y += bfv.y; pif.z += bfv.z; pif.w += bfv.w;
        pis.x += bsv.x; pis.y += bsv.y; pis.z += bsv.z; pis.w += bsv.w;
        int k = g_roff[i];
        int end = g_cursor[i];
        float4 acc = make_float4(0.f, 0.f, 0.f, 0.f);

        for (; k + 4 <= end; k += 4) {
            int2 p0 = g_epack[k], p1 = g_epack[k + 1];
            int2 p2 = g_epack[k + 2], p3 = g_epack[k + 3];
            float4 f0, q0, f1, q1, f2, q2, f3, q3;
            pj_load(p0.x, lane, f0, q0);
            pj_load(p1.x, lane, f1, q1);
            pj_load(p2.x, lane, f2, q2);
            pj_load(p3.x, lane, f3, q3);
            msg_add(acc, pif, pis, f0, q0, __int_as_float(p0.y), wfe, wse);
            msg_add(acc, pif, pis, f1, q1, __int_as_float(p1.y), wfe, wse);
            msg_add(acc, pif, pis, f2, q2, __int_as_float(p2.y), wfe, wse);
            msg_add(acc, pif, pis, f3, q3, __int_as_float(p3.y), wfe, wse);
        }
        for (; k < end; k++) {
            int2 p0 = g_epack[k];
            float4 f0, q0;
            pj_load(p0.x, lane, f0, q0);
            msg_add(acc, pif, pis, f0, q0, __int_as_float(p0.y), wfe, wse);
        }
        *(float4*)(g_aggr + (size_t)i * CC + c) = acc;
        lsum[0] += acc.x; lsum[1] += acc.y; lsum[2] += acc.z; lsum[3] += acc.w;
        lsq[0] += acc.x * acc.x; lsq[1] += acc.y * acc.y; lsq[2] += acc.z * acc.z; lsq[3] += acc.w * acc.w;

        i = __shfl_sync(0xFFFFFFFFu, nexti, 0);
    }

#pragma unroll
    for (int j = 0; j < 4; j++) {
        atomicAdd(&s_stats[c + j], lsum[j]);
        atomicAdd(&s_stats[CC + c + j], lsq[j]);
    }
    __syncthreads();
    if (tid < 64) {
        float4 v = *(float4*)&s_stats[tid * 4];
        float* dstp = g_stats + tid * 4;
        asm volatile("red.global.add.v4.f32 [%0], {%1, %2, %3, %4};"
                     :: "l"(dstp), "f"(v.x), "f"(v.y), "f"(v.z), "f"(v.w)
                     : "memory");
    }
}

// ---------------- out_final = 2*out + batchnorm(aggr) ----------------
__global__ void finalize(const float* __restrict__ gamma, const float* __restrict__ beta,
                         float* __restrict__ out) {
    int i4 = blockIdx.x * blockDim.x + threadIdx.x;
    if (i4 >= NN * 32) return;
    int c = (i4 & 31) * 4;
    float4 a = *(const float4*)(g_aggr + (size_t)i4 * 4);
    float4 o = *(const float4*)(g_out + (size_t)i4 * 4);
    const float inv = 1.0f / NN;
    float4 r;
#pragma unroll
    for (int j = 0; j < 4; j++) {
        float sum = g_stats[c + j];
        float sq = g_stats[CC + c + j];
        float mean = sum * inv;
        float var = sq * inv - mean * mean;
        float scale = rsqrtf(var + 1e-5f) * gamma[c + j];
        float av = (&a.x)[j];
        float ov = (&o.x)[j];
        (&r.x)[j] = 2.0f * ov + (av - mean) * scale + beta[c + j];
    }
    *(float4*)(out + (size_t)i4 * 4) = r;
}

extern "C" void kernel_launch(void* const* d_in, const int* in_sizes, int n_in,
                              void* d_out, int out_size) {
    const float* h    = (const float*)d_in[0];
    const int*   ei   = (const int*)d_in[1];
    const float* ea   = (const float*)d_in[3];
    const float* W0   = (const float*)d_in[4];
    const float* b0   = (const float*)d_in[5];
    const float* Wsh  = (const float*)d_in[6];
    const float* bsh  = (const float*)d_in[7];
    const float* Wf   = (const float*)d_in[8];
    const float* bf   = (const float*)d_in[9];
    const float* Ws   = (const float*)d_in[10];
    const float* bs   = (const float*)d_in[11];
    const float* gamma = (const float*)d_in[12];
    const float* beta  = (const float*)d_in[13];
    float* out = (float*)d_out;

    int *p_deg;
    cudaGetSymbolAddress((void**)&p_deg, g_deg);

    // BOTH branches on non-legacy streams for a truly parallel captured DAG.
    static cudaStream_t s2 = nullptr, s3 = nullptr;
    static cudaEvent_t evFork = nullptr, evJoin2 = nullptr, evJoin3 = nullptr;
    static bool attrSet = false;
    const int SMEM_NG = 2 * 128 * LDH * (int)sizeof(__half);
    if (!s2) {
        cudaStreamCreateWithFlags(&s2, cudaStreamNonBlocking);
        cudaStreamCreateWithFlags(&s3, cudaStreamNonBlocking);
        cudaEventCreateWithFlags(&evFork, cudaEventDisableTiming);
        cudaEventCreateWithFlags(&evJoin2, cudaEventDisableTiming);
        cudaEventCreateWithFlags(&evJoin3, cudaEventDisableTiming);
    }
    if (!attrSet) {
        cudaFuncSetAttribute(node_gemms, cudaFuncAttributeMaxDynamicSharedMemorySize, SMEM_NG);
        attrSet = true;
    }

    // ---- fork ----
    cudaEventRecord(evFork, 0);
    cudaStreamWaitEvent(s2, evFork, 0);
    cudaStreamWaitEvent(s3, evFork, 0);

    // branch A (s2): CSR build + edge gaussian (memory-bound)
    cudaMemsetAsync(p_deg, 0, NN * sizeof(int), s2);
    hist<<<(EE + 255) / 256, 256, 0, s2>>>(ei);
    assign_off<<<(NN + 255) / 256, 256, 0, s2>>>();
    edge_gauss_scatter<<<(EE * 8 + 255) / 256, 256, 0, s2>>>(ea, Wsh, bsh, ei);
    cudaEventRecord(evJoin2, s2);

    // branch B (s3): weight pack + fused node GEMMs (tensor core)
    prep_pack<<<(640 * 128 + 255) / 256, 256, 0, s3>>>(W0, Wf, Ws);
    node_gemms<<<(NN + 127) / 128, 256, SMEM_NG, s3>>>(h, b0);
    cudaEventRecord(evJoin3, s3);

    // ---- join ----
    cudaStreamWaitEvent(0, evJoin2, 0);
    cudaStreamWaitEvent(0, evJoin3, 0);

    edge_msg_csr<<<1024, 256>>>(Wf, Ws, bf, bs);
    finalize<<<(NN * 32 + 255) / 256, 256>>>(gamma, beta, out);
}

// round 15
// speedup vs baseline: 1.2196x; 1.0071x over previous
#include <cuda_runtime.h>
#include <cuda_fp16.h>
#include <math.h>

#define NN 50000
#define EE 600000
#define CC 128
#define KK 128
#define LDH 136                           // padded smem row, halves (68 half2)

// Scratch (static device globals; no runtime allocation allowed)
__device__ float  g_out[(size_t)NN * CC];      // softplus(h@W0+b0) fp32
__device__ float  g_Pi[(size_t)NN * 256];      // fp32 [pi_f | pi_s] per node
// INTERLEAVED fp16 pj: lane l: halves [8l,8l+4) = f ch 4l..4l+3, [8l+4,8l+8) = q.
__device__ __half g_Pj16[(size_t)NN * 256];
__device__ float  g_aggr[(size_t)NN * CC];     // segment-sum result
__device__ float  g_stats[2 * CC];             // per-channel sum, sumsq
__device__ __half g_W016T[128 * 128];          // W0 transposed [n][k], fp16
__device__ __half g_Wcat16T[512 * 128];        // packed weights, TRANSPOSED [n][k], fp16
// CSR scratch (g_deg is SELF-CLEANING: statics start 0; assign_off re-zeroes
// after reading, so every graph replay sees deg==0 at hist time)
__device__ int    g_deg[NN];
__device__ int    g_roff[NN];
__device__ int    g_cursor[NN];
__device__ int    g_total;
__device__ int    g_ticket;                    // work-steal counter for edge_msg
__device__ int2   g_epack[EE];                 // (src, e-bits) grouped by dst row

__device__ __forceinline__ float sp_f(float x) {
    return x > 15.0f ? x : __logf(1.0f + __expf(x));
}
__device__ __forceinline__ float sigm_f(float x) {
    float t;
    asm("tanh.approx.f32 %0, %1;" : "=f"(t) : "f"(x * 0.5f));
    return fmaf(0.5f, t, 0.5f);
}

// ---------------- weight packing: W0T + WcatT (fp16, [n][k]) + zero stats ----
__global__ void prep_pack(const float* __restrict__ W0,
                          const float* __restrict__ Wf, const float* __restrict__ Ws) {
    int idx = blockIdx.x * blockDim.x + threadIdx.x;   // n_all*128 + k, n_all 0..639
    if (idx < 640 * 128) {
        int n_all = idx >> 7;
        int k = idx & 127;
        float v;
        if (n_all < 128) {
            v = W0[k * 128 + n_all];
            g_W016T[idx] = __float2half(v);
        } else {
            int n = n_all - 128;
            if (n < 128)      v = Wf[k * 128 + n];
            else if (n < 256) v = Ws[k * 128 + (n - 128)];
            else if (n < 384) v = Wf[(128 + k) * 128 + (n - 256)];
            else              v = Ws[(128 + k) * 128 + (n - 384)];
            g_Wcat16T[(size_t)n * 128 + k] = __float2half(v);
        }
    }
    if (blockIdx.x == 0) {
        if (threadIdx.x < 2 * CC) g_stats[threadIdx.x] = 0.0f;
        if (threadIdx.x == 0) g_ticket = 0;
    }
}

// ---------------- Fused node GEMMs (fp16 tensor core) ----------------------
__global__ void __launch_bounds__(256, 2)
node_gemms(const float* __restrict__ h, const float* __restrict__ bias) {
    extern __shared__ __half smemh[];
    __half* As = smemh;                 // [128][LDH]  (h16, then out16)
    __half* Bs = smemh + 128 * LDH;     // [128][LDH]  (weight tiles [n][k])
    int tid = threadIdx.x;
    int row0 = blockIdx.x * 128;

    // Load h tile fp32 -> fp16 smem
#pragma unroll
    for (int l = 0; l < 16; l++) {
        int f = tid + l * 256;
        int r = f >> 5;
        int c4 = (f & 31) << 2;
        int gr = row0 + r;
        float4 v = make_float4(0.f, 0.f, 0.f, 0.f);
        if (gr < NN) v = *(const float4*)(h + (size_t)gr * KK + c4);
        __half2 h0 = __floats2half2_rn(v.x, v.y);
        __half2 h1 = __floats2half2_rn(v.z, v.w);
        uint2 u;
        u.x = *(unsigned*)&h0;
        u.y = *(unsigned*)&h1;
        *(uint2*)(As + r * LDH + c4) = u;
    }
#pragma unroll
    for (int l = 0; l < 8; l++) {
        int idx = tid + l * 256;
        int r = idx >> 4;
        int c8 = (idx & 15) << 3;
        *(int4*)(Bs + r * LDH + c8) = *(const int4*)(g_W016T + (size_t)r * CC + c8);
    }
    __syncthreads();

    int lane = tid & 31;
    int w = tid >> 5;
    int g = lane >> 2, tig = lane & 3;
    int wm = (w & 1) * 64, wn = (w >> 1) * 32;

    const unsigned* As2 = (const unsigned*)As;
    const unsigned* Bs2 = (const unsigned*)Bs;

    float acc[4][4][4];

    // ---- Stage 1: h @ W0 ----
#pragma unroll
    for (int mt = 0; mt < 4; mt++)
#pragma unroll
        for (int nt = 0; nt < 4; nt++)
#pragma unroll
            for (int q = 0; q < 4; q++) acc[mt][nt][q] = 0.f;

#pragma unroll
    for (int ks = 0; ks < 8; ks++) {
        int kk = ks * 8;
        unsigned a[4][4], b[4][2];
#pragma unroll
        for (int mt = 0; mt < 4; mt++) {
            int r = wm + mt * 16 + g;
            a[mt][0] = As2[r * 68 + kk + tig];
            a[mt][1] = As2[(r + 8) * 68 + kk + tig];
            a[mt][2] = As2[r * 68 + kk + 4 + tig];
            a[mt][3] = As2[(r + 8) * 68 + kk + 4 + tig];
        }
#pragma unroll
        for (int nt = 0; nt < 4; nt++) {
            int r = wn + nt * 8 + g;
            b[nt][0] = Bs2[r * 68 + kk + tig];
            b[nt][1] = Bs2[r * 68 + kk + 4 + tig];
        }
#pragma unroll
        for (int mt = 0; mt < 4; mt++)
#pragma unroll
            for (int nt = 0; nt < 4; nt++) {
                asm volatile(
                    "mma.sync.aligned.m16n8k16.row.col.f32.f16.f16.f32 "
                    "{%0,%1,%2,%3}, {%4,%5,%6,%7}, {%8,%9}, {%0,%1,%2,%3};"
                    : "+f"(acc[mt][nt][0]), "+f"(acc[mt][nt][1]),
                      "+f"(acc[mt][nt][2]), "+f"(acc[mt][nt][3])
                    : "r"(a[mt][0]), "r"(a[mt][1]), "r"(a[mt][2]), "r"(a[mt][3]),
                      "r"(b[nt][0]), "r"(b[nt][1]));
            }
    }
    __syncthreads();

    // Stage-1 epilogue: softplus + bias -> g_out fp32, out16 -> As (reuse)
#pragma unroll
    for (int mt = 0; mt < 4; mt++) {
#pragma unroll
        for (int nt = 0; nt < 4; nt++) {
            int r0 = wm + mt * 16 + g;
            int r1 = r0 + 8;
            int col = wn + nt * 8 + tig * 2;
            float bb0 = bias[col], bb1 = bias[col + 1];
            float o0 = sp_f(acc[mt][nt][0] + bb0);
            float o1 = sp_f(acc[mt][nt][1] + bb1);
            float o2 = sp_f(acc[mt][nt][2] + bb0);
            float o3 = sp_f(acc[mt][nt][3] + bb1);
            __half2 h01 = __floats2half2_rn(o0, o1);
            __half2 h23 = __floats2half2_rn(o2, o3);
            *(unsigned*)(As + r0 * LDH + col) = *(unsigned*)&h01;
            *(unsigned*)(As + r1 * LDH + col) = *(unsigned*)&h23;
            int gr0 = row0 + r0, gr1 = row0 + r1;
            if (gr0 < NN) *(float2*)(g_out + (size_t)gr0 * CC + col) = make_float2(o0, o1);
            if (gr1 < NN) *(float2*)(g_out + (size_t)gr1 * CC + col) = make_float2(o2, o3);
        }
    }
    __syncthreads();

    // ---- Stage 2: out @ Wcat, 4 n-blocks ----
    for (int nblk = 0; nblk < 4; nblk++) {
#pragma unroll
        for (int l = 0; l < 8; l++) {
            int idx = tid + l * 256;
            int r = idx >> 4;
            int c8 = (idx & 15) << 3;
            *(int4*)(Bs + r * LDH + c8) =
                *(const int4*)(g_Wcat16T + ((size_t)(nblk * 128 + r)) * CC + c8);
        }
        __syncthreads();

#pragma unroll
        for (int mt = 0; mt < 4; mt++)
#pragma unroll
            for (int nt = 0; nt < 4; nt++)
#pragma unroll
                for (int q = 0; q < 4; q++) acc[mt][nt][q] = 0.f;

#pragma unroll
        for (int ks = 0; ks < 8; ks++) {
            int kk = ks * 8;
            unsigned a[4][4], b[4][2];
#pragma unroll
            for (int mt = 0; mt < 4; mt++) {
                int r = wm + mt * 16 + g;
                a[mt][0] = As2[r * 68 + kk + tig];
                a[mt][1] = As2[(r + 8) * 68 + kk + tig];
                a[mt][2] = As2[r * 68 + kk + 4 + tig];
                a[mt][3] = As2[(r + 8) * 68 + kk + 4 + tig];
            }
#pragma unroll
            for (int nt = 0; nt < 4; nt++) {
                int r = wn + nt * 8 + g;
                b[nt][0] = Bs2[r * 68 + kk + tig];
                b[nt][1] = Bs2[r * 68 + kk + 4 + tig];
            }
#pragma unroll
            for (int mt = 0; mt < 4; mt++)
#pragma unroll
                for (int nt = 0; nt < 4; nt++) {
                    asm volatile(
                        "mma.sync.aligned.m16n8k16.row.col.f32.f16.f16.f32 "
                        "{%0,%1,%2,%3}, {%4,%5,%6,%7}, {%8,%9}, {%0,%1,%2,%3};"
                        : "+f"(acc[mt][nt][0]), "+f"(acc[mt][nt][1]),
                          "+f"(acc[mt][nt][2]), "+f"(acc[mt][nt][3])
                        : "r"(a[mt][0]), "r"(a[mt][1]), "r"(a[mt][2]), "r"(a[mt][3]),
                          "r"(b[nt][0]), "r"(b[nt][1]));
                }
        }

#pragma unroll
        for (int mt = 0; mt < 4; mt++) {
#pragma unroll
            for (int nt = 0; nt < 4; nt++) {
                int gr0 = row0 + wm + mt * 16 + g;
                int gr1 = gr0 + 8;
                float d0 = acc[mt][nt][0], d1 = acc[mt][nt][1];
                float d2 = acc[mt][nt][2], d3 = acc[mt][nt][3];
                if (nblk < 2) {
                    int col = nblk * 128 + wn + nt * 8 + tig * 2;
                    if (gr0 < NN) *(float2*)(g_Pi + (size_t)gr0 * 256 + col) = make_float2(d0, d1);
                    if (gr1 < NN) *(float2*)(g_Pi + (size_t)gr1 * 256 + col) = make_float2(d2, d3);
                } else {
                    int c0 = wn + nt * 8 + tig * 2;
                    int hoff = ((c0 >> 2) << 3) + (c0 & 3) + (nblk == 3 ? 4 : 0);
                    __half2 h01 = __floats2half2_rn(d0, d1);
                    __half2 h23 = __floats2half2_rn(d2, d3);
                    if (gr0 < NN) *(unsigned*)(g_Pj16 + (size_t)gr0 * 256 + hoff) = *(unsigned*)&h01;
                    if (gr1 < NN) *(unsigned*)(g_Pj16 + (size_t)gr1 * 256 + hoff) = *(unsigned*)&h23;
                }
            }
        }
        __syncthreads();
    }
}

// ---------------- CSR build ----------------
__global__ void hist(const int* __restrict__ ei) {
    int e = blockIdx.x * blockDim.x + threadIdx.x;
    if (e == 0) g_total = 0;
    if (e < EE) atomicAdd(&g_deg[ei[EE + e]], 1);
}

// Reads deg, assigns row offsets, then SELF-CLEANS deg for the next replay.
__global__ void assign_off() {
    int i = blockIdx.x * blockDim.x + threadIdx.x;
    if (i < NN) {
        int d = g_deg[i];
        g_deg[i] = 0;                    // self-clean (replaces host memset)
        int r = atomicAdd(&g_total, d);
        g_roff[i] = r;
        g_cursor[i] = r;
    }
}

// ---------------- e = softplus(edge_attr @ Wsh + bsh) fused with CSR scatter
__global__ void edge_gauss_scatter(const float* __restrict__ ea,
                                   const float* __restrict__ Wsh,
                                   const float* __restrict__ bsh,
                                   const int* __restrict__ ei) {
    int t = blockIdx.x * blockDim.x + threadIdx.x;
    int e = t >> 3;
    if (e >= EE) return;
    int l = t & 7;
    const float4* base = (const float4*)(ea + (size_t)e * 128) + l * 4;
    const float4* wb = (const float4*)Wsh + l * 4;
    float4 a0 = base[0], a1 = base[1], a2 = base[2], a3 = base[3];
    float4 w0 = wb[0], w1 = wb[1], w2 = wb[2], w3 = wb[3];
    float d = a0.x * w0.x + a0.y * w0.y + a0.z * w0.z + a0.w * w0.w
            + a1.x * w1.x + a1.y * w1.y + a1.z * w1.z + a1.w * w1.w
            + a2.x * w2.x + a2.y * w2.y + a2.z * w2.z + a2.w * w2.w
            + a3.x * w3.x + a3.y * w3.y + a3.z * w3.z + a3.w * w3.w;
#pragma unroll
    for (int o = 4; o; o >>= 1) d += __shfl_xor_sync(0xFFFFFFFFu, d, o);
    if (l == 0) {
        float ev = sp_f(d + bsh[0]);
        int src = __ldg(ei + e);
        int dst = __ldg(ei + EE + e);
        int pos = atomicAdd(&g_cursor[dst], 1);
        g_epack[pos] = make_int2(src, __float_as_int(ev));
    }
}

// ---------------- CSR edge messages + fused BN stats (work-stealing) ------
__device__ __forceinline__ void pj_load(int src, int lane, float4& f, float4& q) {
    uint4 v = *(const uint4*)(g_Pj16 + (size_t)src * 256 + lane * 8);
    float2 f01 = __half22float2(*(__half2*)&v.x);
    float2 f23 = __half22float2(*(__half2*)&v.y);
    float2 q01 = __half22float2(*(__half2*)&v.z);
    float2 q23 = __half22float2(*(__half2*)&v.w);
    f = make_float4(f01.x, f01.y, f23.x, f23.y);
    q = make_float4(q01.x, q01.y, q23.x, q23.y);
}

__device__ __forceinline__ void msg_add(float4& acc, const float4& pif, const float4& pis,
                                        const float4& f, const float4& q, float ev,
                                        const float4& wfe, const float4& wse) {
    acc.x += sigm_f(pif.x + f.x + ev * wfe.x) * sp_f(pis.x + q.x + ev * wse.x);
    acc.y += sigm_f(pif.y + f.y + ev * wfe.y) * sp_f(pis.y + q.y + ev * wse.y);
    acc.z += sigm_f(pif.z + f.z + ev * wfe.z) * sp_f(pis.z + q.z + ev * wse.z);
    acc.w += sigm_f(pif.w + f.w + ev * wfe.w) * sp_f(pis.w + q.w + ev * wse.w);
}

__global__ void __launch_bounds__(256)
edge_msg_csr(const float* __restrict__ Wf, const float* __restrict__ Ws,
             const float* __restrict__ bf, const float* __restrict__ bs) {
    __shared__ float s_stats[2 * CC];
    int tid = threadIdx.x;
    int lane = tid & 31;
    int c = lane * 4;
    s_stats[tid] = 0.0f;
    __syncthreads();

    float4 wfe = *(const float4*)(Wf + 256 * 128 + c);
    float4 wse = *(const float4*)(Ws + 256 * 128 + c);
    float4 bfv = *(const float4*)(bf + c);
    float4 bsv = *(const float4*)(bs + c);

    float lsum[4] = {}, lsq[4] = {};

    int i = 0;
    if (lane == 0) i = atomicAdd(&g_ticket, 1);
    i = __shfl_sync(0xFFFFFFFFu, i, 0);

    while (i < NN) {
        int nexti = 0;
        if (lane == 0) nexti = atomicAdd(&g_ticket, 1);   // prefetch next ticket

        const float4* Pi = (const float4*)(g_Pi + (size_t)i * 256);
        float4 pif = Pi[lane];
        float4 pis = Pi[32 + lane];
        pif.x += bfv.x; pif.y += bfv.y; pif.z += bfv.z; pif.w += bfv.w;
        pis.x += bsv.x; pis.y += bsv.y; pis.z += bsv.z; pis.w += bsv.w;
        int k = g_roff[i];
        int end = g_cursor[i];
        float4 acc = make_float4(0.f, 0.f, 0.f, 0.f);

        for (; k + 4 <= end; k += 4) {
            int2 p0 = g_epack[k], p1 = g_epack[k + 1];
            int2 p2 = g_epack[k + 2], p3 = g_epack[k + 3];
            float4 f0, q0, f1, q1, f2, q2, f3, q3;
            pj_load(p0.x, lane, f0, q0);
            pj_load(p1.x, lane, f1, q1);
            pj_load(p2.x, lane, f2, q2);
            pj_load(p3.x, lane, f3, q3);
            msg_add(acc, pif, pis, f0, q0, __int_as_float(p0.y), wfe, wse);
            msg_add(acc, pif, pis, f1, q1, __int_as_float(p1.y), wfe, wse);
            msg_add(acc, pif, pis, f2, q2, __int_as_float(p2.y), wfe, wse);
            msg_add(acc, pif, pis, f3, q3, __int_as_float(p3.y), wfe, wse);
        }
        for (; k < end; k++) {
            int2 p0 = g_epack[k];
            float4 f0, q0;
            pj_load(p0.x, lane, f0, q0);
            msg_add(acc, pif, pis, f0, q0, __int_as_float(p0.y), wfe, wse);
        }
        *(float4*)(g_aggr + (size_t)i * CC + c) = acc;
        lsum[0] += acc.x; lsum[1] += acc.y; lsum[2] += acc.z; lsum[3] += acc.w;
        lsq[0] += acc.x * acc.x; lsq[1] += acc.y * acc.y; lsq[2] += acc.z * acc.z; lsq[3] += acc.w * acc.w;

        i = __shfl_sync(0xFFFFFFFFu, nexti, 0);
    }

#pragma unroll
    for (int j = 0; j < 4; j++) {
        atomicAdd(&s_stats[c + j], lsum[j]);
        atomicAdd(&s_stats[CC + c + j], lsq[j]);
    }
    __syncthreads();
    if (tid < 64) {
        float4 v = *(float4*)&s_stats[tid * 4];
        float* dstp = g_stats + tid * 4;
        asm volatile("red.global.add.v4.f32 [%0], {%1, %2, %3, %4};"
                     :: "l"(dstp), "f"(v.x), "f"(v.y), "f"(v.z), "f"(v.w)
                     : "memory");
    }
}

// ---------------- out_final = 2*out + batchnorm(aggr) ----------------
__global__ void finalize(const float* __restrict__ gamma, const float* __restrict__ beta,
                         float* __restrict__ out) {
    int i4 = blockIdx.x * blockDim.x + threadIdx.x;
    if (i4 >= NN * 32) return;
    int c = (i4 & 31) * 4;
    float4 a = *(const float4*)(g_aggr + (size_t)i4 * 4);
    float4 o = *(const float4*)(g_out + (size_t)i4 * 4);
    const float inv = 1.0f / NN;
    float4 r;
#pragma unroll
    for (int j = 0; j < 4; j++) {
        float sum = g_stats[c + j];
        float sq = g_stats[CC + c + j];
        float mean = sum * inv;
        float var = sq * inv - mean * mean;
        float scale = rsqrtf(var + 1e-5f) * gamma[c + j];
        float av = (&a.x)[j];
        float ov = (&o.x)[j];
        (&r.x)[j] = 2.0f * ov + (av - mean) * scale + beta[c + j];
    }
    *(float4*)(out + (size_t)i4 * 4) = r;
}

extern "C" void kernel_launch(void* const* d_in, const int* in_sizes, int n_in,
                              void* d_out, int out_size) {
    const float* h    = (const float*)d_in[0];
    const int*   ei   = (const int*)d_in[1];
    const float* ea   = (const float*)d_in[3];
    const float* W0   = (const float*)d_in[4];
    const float* b0   = (const float*)d_in[5];
    const float* Wsh  = (const float*)d_in[6];
    const float* bsh  = (const float*)d_in[7];
    const float* Wf   = (const float*)d_in[8];
    const float* bf   = (const float*)d_in[9];
    const float* Ws   = (const float*)d_in[10];
    const float* bs   = (const float*)d_in[11];
    const float* gamma = (const float*)d_in[12];
    const float* beta  = (const float*)d_in[13];
    float* out = (float*)d_out;

    // BOTH branches on non-legacy streams for a truly parallel captured DAG.
    static cudaStream_t s2 = nullptr, s3 = nullptr;
    static cudaEvent_t evFork = nullptr, evJoin2 = nullptr, evJoin3 = nullptr;
    static bool attrSet = false;
    const int SMEM_NG = 2 * 128 * LDH * (int)sizeof(__half);
    if (!s2) {
        cudaStreamCreateWithFlags(&s2, cudaStreamNonBlocking);
        cudaStreamCreateWithFlags(&s3, cudaStreamNonBlocking);
        cudaEventCreateWithFlags(&evFork, cudaEventDisableTiming);
        cudaEventCreateWithFlags(&evJoin2, cudaEventDisableTiming);
        cudaEventCreateWithFlags(&evJoin3, cudaEventDisableTiming);
    }
    if (!attrSet) {
        cudaFuncSetAttribute(node_gemms, cudaFuncAttributeMaxDynamicSharedMemorySize, SMEM_NG);
        attrSet = true;
    }

    // ---- fork ----
    cudaEventRecord(evFork, 0);
    cudaStreamWaitEvent(s2, evFork, 0);
    cudaStreamWaitEvent(s3, evFork, 0);

    // branch A (s2): CSR build + edge gaussian. NO memsets — deg self-cleans.
    hist<<<(EE + 255) / 256, 256, 0, s2>>>(ei);
    assign_off<<<(NN + 255) / 256, 256, 0, s2>>>();
    edge_gauss_scatter<<<(EE * 8 + 255) / 256, 256, 0, s2>>>(ea, Wsh, bsh, ei);
    cudaEventRecord(evJoin2, s2);

    // branch B (s3): weight pack + fused node GEMMs (tensor core)
    prep_pack<<<(640 * 128 + 255) / 256, 256, 0, s3>>>(W0, Wf, Ws);
    node_gemms<<<(NN + 127) / 128, 256, SMEM_NG, s3>>>(h, b0);
    cudaEventRecord(evJoin3, s3);

    // ---- join: exactly 5 kernels precede edge_msg, all dependencies ----
    cudaStreamWaitEvent(0, evJoin2, 0);
    cudaStreamWaitEvent(0, evJoin3, 0);

    edge_msg_csr<<<1024, 256>>>(Wf, Ws, bf, bs);
    finalize<<<(NN * 32 + 255) / 256, 256>>>(gamma, beta, out);
}